// round 3
// baseline (speedup 1.0000x reference)
#include <cuda_runtime.h>
#include <math.h>

#define DEV_INLINE __device__ __forceinline__

constexpr int B_ = 2, Q_ = 75, N_ = 5, T_ = 196, C_ = 384, H_ = 1536;
constexpr float TEMP_ = 10.0f;

// ---------------- scratch (device globals; no allocation) ----------------
__device__ float g_part[B_ * N_ * 4 * C_];      // partial t-sums of feat_shot
__device__ float g_mean_cls[B_ * N_ * C_];
__device__ float g_mean_task[B_ * C_];
__device__ float g_hidden[(B_ + B_ * N_) * H_]; // rows 0..1 task, 2..11 cls
__device__ float g_wt[B_ * C_];
__device__ float g_wc[B_ * N_ * C_];
__device__ float g_u[B_ * N_ * C_];             // wc * wt
__device__ float g_ns[B_ * N_ * T_];            // ||fs[b,n,t,:]||
__device__ float g_xsrw[B_ * N_ * C_];          // normalized reweighted shot vec
__device__ float g_xshat[B_ * N_ * C_];         // normalized x_shot
__device__ float g_num[B_ * Q_ * N_ * T_];      // fq . fs
__device__ float g_dq[B_ * Q_ * N_ * T_];       // fq . u  (map_q logits)
__device__ float g_nq[B_ * Q_ * T_];            // ||fq[b,q,t,:]||

// ---------------- reduction helpers ----------------
DEV_INLINE float blockReduceSum1(float v, float* red, int tid) {
    #pragma unroll
    for (int o = 16; o; o >>= 1) v += __shfl_xor_sync(0xffffffffu, v, o);
    int warp = tid >> 5, lane = tid & 31;
    int nw = blockDim.x >> 5;
    __syncthreads();
    if (lane == 0) red[warp] = v;
    __syncthreads();
    if (tid == 0) {
        float s = 0.f;
        for (int w = 0; w < nw; w++) s += red[w];
        red[0] = s;
    }
    __syncthreads();
    float r = red[0];
    __syncthreads();
    return r;
}

template <int NV>
DEV_INLINE void blockReduceSumArr(float* v, float* red, int tid) {
    #pragma unroll
    for (int i = 0; i < NV; i++)
        #pragma unroll
        for (int o = 16; o; o >>= 1) v[i] += __shfl_xor_sync(0xffffffffu, v[i], o);
    int warp = tid >> 5, lane = tid & 31;
    int nw = blockDim.x >> 5;
    __syncthreads();
    if (lane == 0)
        #pragma unroll
        for (int i = 0; i < NV; i++) red[warp * NV + i] = v[i];
    __syncthreads();
    if (tid == 0) {
        for (int w = 1; w < nw; w++)
            #pragma unroll
            for (int i = 0; i < NV; i++) red[i] += red[w * NV + i];
    }
    __syncthreads();
    #pragma unroll
    for (int i = 0; i < NV; i++) v[i] = red[i];
    __syncthreads();
}

template <int NV>
DEV_INLINE void blockReduceMaxArr(float* v, float* red, int tid) {
    #pragma unroll
    for (int i = 0; i < NV; i++)
        #pragma unroll
        for (int o = 16; o; o >>= 1) v[i] = fmaxf(v[i], __shfl_xor_sync(0xffffffffu, v[i], o));
    int warp = tid >> 5, lane = tid & 31;
    int nw = blockDim.x >> 5;
    __syncthreads();
    if (lane == 0)
        #pragma unroll
        for (int i = 0; i < NV; i++) red[warp * NV + i] = v[i];
    __syncthreads();
    if (tid == 0) {
        for (int w = 1; w < nw; w++)
            #pragma unroll
            for (int i = 0; i < NV; i++) red[i] = fmaxf(red[i], red[w * NV + i]);
    }
    __syncthreads();
    #pragma unroll
    for (int i = 0; i < NV; i++) v[i] = red[i];
    __syncthreads();
}

DEV_INLINE float sigmoidf(float x) { return 1.f / (1.f + expf(-x)); }

// ---------------- K1: feat_shot means ----------------
// grid (4 t-chunks, B*N), 384 threads: partial sums over 49 t's
__global__ void k1_partial(const float* __restrict__ feat_shot) {
    int bn = blockIdx.y, chunk = blockIdx.x, c = threadIdx.x;
    const float* p = feat_shot + ((size_t)bn * T_ + chunk * 49) * C_ + c;
    float s = 0.f;
    #pragma unroll 7
    for (int t = 0; t < 49; t++) s += p[t * C_];
    g_part[(bn * 4 + chunk) * C_ + c] = s;
}

// fused: blocks 0..B*N-1 -> mean_cls[bn]; blocks B*N..B*N+B-1 -> mean_task[b]
// (both read only g_part)
__global__ void k1_means_task() {
    int blk = blockIdx.x, c = threadIdx.x;
    if (blk < B_ * N_) {
        int bn = blk;
        float s = 0.f;
        #pragma unroll
        for (int k = 0; k < 4; k++) s += g_part[(bn * 4 + k) * C_ + c];
        g_mean_cls[bn * C_ + c] = s * (1.f / T_);
    } else {
        int b = blk - B_ * N_;
        float s = 0.f;
        #pragma unroll
        for (int n = 0; n < N_; n++) {
            float sn = 0.f;
            #pragma unroll
            for (int k = 0; k < 4; k++) sn += g_part[((b * N_ + n) * 4 + k) * C_ + c];
            s += sn * (1.f / T_);   // per-class mean, then mean over n (matches prior order)
        }
        g_mean_task[b * C_ + c] = s * (1.f / N_);
    }
}

// ---------------- K2: tiny MLPs ----------------
// layer 1: 12 rows x H.  grid = H/128 blocks, 256 threads (2 c-halves x 128 j)
__global__ void k2_mlp1(const float* __restrict__ w1t, const float* __restrict__ b1t,
                        const float* __restrict__ w1c, const float* __restrict__ b1c) {
    __shared__ float xs[12 * C_];
    __shared__ float part[12 * 128];
    int tid = threadIdx.x;
    for (int i = tid; i < 12 * C_; i += 256) {
        int r = i / C_, c = i % C_;
        xs[i] = (r < B_) ? g_mean_task[r * C_ + c] : g_mean_cls[(r - B_) * C_ + c];
    }
    __syncthreads();
    int half = tid >> 7, jj = tid & 127;
    int j = blockIdx.x * 128 + jj;
    float acc[12];
    #pragma unroll
    for (int r = 0; r < 12; r++) acc[r] = 0.f;
    int c0 = half * 192;
    for (int c = c0; c < c0 + 192; c++) {
        float wt = w1t[(size_t)c * H_ + j];
        float wc = w1c[(size_t)c * H_ + j];
        acc[0] += xs[0 * C_ + c] * wt;
        acc[1] += xs[1 * C_ + c] * wt;
        #pragma unroll
        for (int r = 2; r < 12; r++) acc[r] += xs[r * C_ + c] * wc;
    }
    if (half == 1) {
        #pragma unroll
        for (int r = 0; r < 12; r++) part[r * 128 + jj] = acc[r];
    }
    __syncthreads();
    if (half == 0) {
        #pragma unroll
        for (int r = 0; r < 12; r++) {
            float bias = (r < B_) ? b1t[j] : b1c[j];
            float v = acc[r] + part[r * 128 + jj] + bias;
            g_hidden[r * H_ + j] = fmaxf(v, 0.f);
        }
    }
}

// layer 2: grid (3 c-chunks, 12 rows), 256 threads (2 j-halves x 128 c)
__global__ void k2_mlp2(const float* __restrict__ w2t, const float* __restrict__ b2t,
                        const float* __restrict__ w2c, const float* __restrict__ b2c) {
    __shared__ float hid[H_];
    __shared__ float part[128];
    int row = blockIdx.y, chunk = blockIdx.x, tid = threadIdx.x;
    for (int i = tid; i < H_; i += 256) hid[i] = g_hidden[row * H_ + i];
    __syncthreads();
    int jh = tid >> 7, cc = tid & 127;
    int c = chunk * 128 + cc;
    const float* w2 = (row < B_) ? w2t : w2c;
    float acc = 0.f;
    int j0 = jh * 768;
    for (int j = j0; j < j0 + 768; j++) acc += hid[j] * w2[(size_t)j * C_ + c];
    if (jh == 1) part[cc] = acc;
    __syncthreads();
    if (jh == 0) {
        float bias = (row < B_) ? b2t[c] : b2c[c];
        float v = acc + part[cc] + bias;
        if (row < B_) g_wt[row * C_ + c] = v;
        else          g_wc[(row - B_) * C_ + c] = sigmoidf(v);
    }
}

// ---------------- K2c: shot-side (per b,n): u, ns, map_s, xs_rw, xs_hat ----------------
__global__ void k2c_shot(const float* __restrict__ feat_shot, const float* __restrict__ x_shot) {
    __shared__ float u_s[C_];
    __shared__ float map_s[T_];
    __shared__ float red[32];
    int bn = blockIdx.x, b = bn / N_, tid = threadIdx.x;
    int warp = tid >> 5, lane = tid & 31;
    float uval = g_wc[bn * C_ + tid] * g_wt[b * C_ + tid];
    g_u[bn * C_ + tid] = uval;
    u_s[tid] = uval;
    __syncthreads();
    const float* fsr = feat_shot + (size_t)bn * T_ * C_;
    for (int t = warp; t < T_; t += 12) {
        float ss = 0.f, du = 0.f;
        for (int c = lane; c < C_; c += 32) {
            float f = fsr[t * C_ + c];
            ss += f * f;
            du += f * u_s[c];
        }
        #pragma unroll
        for (int o = 16; o; o >>= 1) {
            ss += __shfl_xor_sync(0xffffffffu, ss, o);
            du += __shfl_xor_sync(0xffffffffu, du, o);
        }
        if (lane == 0) {
            g_ns[bn * T_ + t] = sqrtf(ss);
            map_s[t] = sigmoidf(du);
        }
    }
    __syncthreads();
    float a = 0.f;
    for (int t = 0; t < T_; t++) a += fsr[t * C_ + tid] * map_s[t];
    float v = g_wc[bn * C_ + tid] * a * (1.f / T_);
    float s2 = blockReduceSum1(v * v, red, tid);
    g_xsrw[bn * C_ + tid] = v / (1e-16f + sqrtf(s2));
    float xv = x_shot[(size_t)bn * C_ + tid];   // K=1 -> mean over k is identity
    float xn2 = blockReduceSum1(xv * xv, red, tid);
    g_xshat[bn * C_ + tid] = xv / fmaxf(sqrtf(xn2), 1e-12f);
}

// ---------------- K3: pass 1 — num, dq, nq (streams feat_query once) ----------------
// grid (98 t-pairs, B), 256 threads = 8 warps. warp-task = (t in pair, 4-query group)
__global__ void __launch_bounds__(256) k3_pass1(const float* __restrict__ feat_query,
                                                const float* __restrict__ feat_shot) {
    __shared__ float fs_s[2 * N_ * C_];
    __shared__ float u_s[N_ * C_];
    int b = blockIdx.y, t0 = blockIdx.x * 2, tid = threadIdx.x;
    for (int i = tid; i < 2 * N_ * C_; i += 256) {
        int tt = i / (N_ * C_), r = i % (N_ * C_);
        int n = r / C_, c = r % C_;
        fs_s[i] = feat_shot[((size_t)(b * N_ + n) * T_ + t0 + tt) * C_ + c];
    }
    for (int i = tid; i < N_ * C_; i += 256) u_s[i] = g_u[b * N_ * C_ + i];
    __syncthreads();

    int warp = tid >> 5, lane = tid & 31;
    for (int task = warp; task < 38; task += 8) {
        int tt = task / 19, qi = task % 19;
        int t = t0 + tt, q0 = qi * 4;

        float4 fq[4][3];
        #pragma unroll
        for (int qq = 0; qq < 4; qq++) {
            int q = q0 + qq;
            if (q < Q_) {
                const float* p = feat_query + (((size_t)(b * Q_ + q)) * T_ + t) * C_;
                #pragma unroll
                for (int j = 0; j < 3; j++)
                    fq[qq][j] = *(const float4*)(p + 4 * (lane + 32 * j));
            } else {
                #pragma unroll
                for (int j = 0; j < 3; j++) fq[qq][j] = make_float4(0.f, 0.f, 0.f, 0.f);
            }
        }

        // acc layout: [0..19] num(qq*5+n), [20..39] dq, [40..43] nq
        float acc[44];
        #pragma unroll
        for (int i = 0; i < 44; i++) acc[i] = 0.f;

        #pragma unroll
        for (int j = 0; j < 3; j++) {
            int cb = 4 * (lane + 32 * j);
            #pragma unroll
            for (int n = 0; n < N_; n++) {
                float4 s4 = *(const float4*)&fs_s[(tt * N_ + n) * C_ + cb];
                float4 u4 = *(const float4*)&u_s[n * C_ + cb];
                #pragma unroll
                for (int qq = 0; qq < 4; qq++) {
                    float4 f = fq[qq][j];
                    acc[qq * 5 + n]      += f.x * s4.x + f.y * s4.y + f.z * s4.z + f.w * s4.w;
                    acc[20 + qq * 5 + n] += f.x * u4.x + f.y * u4.y + f.z * u4.z + f.w * u4.w;
                }
            }
            #pragma unroll
            for (int qq = 0; qq < 4; qq++) {
                float4 f = fq[qq][j];
                acc[40 + qq] += f.x * f.x + f.y * f.y + f.z * f.z + f.w * f.w;
            }
        }

        #pragma unroll
        for (int i = 0; i < 44; i++)
            #pragma unroll
            for (int o = 16; o; o >>= 1) acc[i] += __shfl_xor_sync(0xffffffffu, acc[i], o);

        if (lane == 0) {
            #pragma unroll
            for (int qq = 0; qq < 4; qq++) {
                int q = q0 + qq;
                if (q < Q_) {
                    size_t base = (size_t)(b * Q_ + q) * N_ * T_;
                    #pragma unroll
                    for (int n = 0; n < N_; n++) {
                        g_num[base + n * T_ + t] = acc[qq * 5 + n];
                        g_dq[base + n * T_ + t]  = acc[20 + qq * 5 + n];
                    }
                    g_nq[(b * Q_ + q) * T_ + t] = sqrtf(acc[40 + qq]);
                }
            }
        }
    }
}

// ---------------- K4: pass 2 — per (b,q): sim/max, acc GEMM, all outputs ----------------
// grid (Q, B), 384 threads (= C)
__global__ void __launch_bounds__(384) k4_pass2(const float* __restrict__ feat_query,
                                                const float* __restrict__ x_query,
                                                float* __restrict__ out) {
    __shared__ float map_s[N_ * T_];      // 980
    __shared__ float4 part4[4 * N_ * 96]; // 30.7 KB
    __shared__ float accf[N_ * C_];       // 7.7 KB
    __shared__ float red[128];

    int q = blockIdx.x, b = blockIdx.y, tid = threadIdx.x;
    int bq = b * Q_ + q;
    size_t nt_base = (size_t)bq * N_ * T_;

    // ---- sim + logits ----
    float mx[N_];
    #pragma unroll
    for (int n = 0; n < N_; n++) mx[n] = -1e30f;
    if (tid < T_) {
        float nqv = g_nq[bq * T_ + tid];
        #pragma unroll
        for (int n = 0; n < N_; n++) {
            float denom = fmaxf(nqv * g_ns[(b * N_ + n) * T_ + tid], 1e-8f);
            mx[n] = g_num[nt_base + n * T_ + tid] / denom;
        }
    }
    blockReduceMaxArr<N_>(mx, red, tid);
    if (tid == 0) {
        float lg = (mx[0] + mx[1] + mx[2] + mx[3] + mx[4]) * (1.f / N_);
        out[bq] = lg;
        out[B_ * Q_ + bq] = lg;   // logits_reweight is identical
    }

    // ---- map_q ----
    for (int i = tid; i < N_ * T_; i += 384) map_s[i] = sigmoidf(g_dq[nt_base + i]);
    __syncthreads();

    // ---- acc[n][c] = sum_t fq[t][c] * map_q[n][t]  (4-way t-split, float4 c) ----
    int g = tid / 96, cg = tid % 96;
    float4 acc[N_];
    #pragma unroll
    for (int n = 0; n < N_; n++) acc[n] = make_float4(0.f, 0.f, 0.f, 0.f);
    const float* fqp = feat_query + ((size_t)bq * T_ + g * 49) * C_ + 4 * cg;
    for (int t = 0; t < 49; t++) {
        float4 f = *(const float4*)(fqp + (size_t)t * C_);
        int tg = g * 49 + t;
        #pragma unroll
        for (int n = 0; n < N_; n++) {
            float m = map_s[n * T_ + tg];
            acc[n].x += f.x * m; acc[n].y += f.y * m;
            acc[n].z += f.z * m; acc[n].w += f.w * m;
        }
    }
    #pragma unroll
    for (int n = 0; n < N_; n++) part4[(g * N_ + n) * 96 + cg] = acc[n];
    __syncthreads();
    for (int idx = tid; idx < N_ * 96; idx += 384) {
        int n = idx / 96, c4 = idx % 96;
        float4 s0 = part4[(0 * N_ + n) * 96 + c4];
        float4 s1 = part4[(1 * N_ + n) * 96 + c4];
        float4 s2 = part4[(2 * N_ + n) * 96 + c4];
        float4 s3 = part4[(3 * N_ + n) * 96 + c4];
        float4 s;
        s.x = s0.x + s1.x + s2.x + s3.x;
        s.y = s0.y + s1.y + s2.y + s3.y;
        s.z = s0.z + s1.z + s2.z + s3.z;
        s.w = s0.w + s1.w + s2.w + s3.w;
        *(float4*)&accf[n * C_ + 4 * c4] = s;
    }
    __syncthreads();

    // ---- cls_logits_reweight ----
    int c = tid;  // 384 threads == C
    #pragma unroll
    for (int n = 0; n < N_; n++) {
        float v = g_wc[(b * N_ + n) * C_ + c] * accf[n * C_ + c] * (1.f / T_);
        float pr[2] = { v * v, v * g_xsrw[(b * N_ + n) * C_ + c] };
        blockReduceSumArr<2>(pr, red, tid);
        if (tid == 0)
            out[2 * B_ * Q_ + B_ * Q_ * N_ + bq * N_ + n] = pr[1] / (1e-16f + sqrtf(pr[0]));
    }

    // ---- cls_logits ----
    float xv = x_query[(size_t)bq * C_ + c];
    float pr6[6];
    pr6[0] = xv * xv;
    #pragma unroll
    for (int n = 0; n < N_; n++) pr6[1 + n] = xv * g_xshat[(b * N_ + n) * C_ + c];
    blockReduceSumArr<6>(pr6, red, tid);
    if (tid == 0) {
        float qn = fmaxf(sqrtf(pr6[0]), 1e-12f);
        #pragma unroll
        for (int n = 0; n < N_; n++)
            out[2 * B_ * Q_ + bq * N_ + n] = TEMP_ * pr6[1 + n] / qn;
    }
}

// ---------------- launch ----------------
extern "C" void kernel_launch(void* const* d_in, const int* in_sizes, int n_in,
                              void* d_out, int out_size) {
    const float* feat_shot  = (const float*)d_in[0];
    const float* feat_query = (const float*)d_in[1];
    const float* x_shot     = (const float*)d_in[2];
    const float* x_query    = (const float*)d_in[3];
    const float* w1_task    = (const float*)d_in[4];
    const float* b1_task    = (const float*)d_in[5];
    const float* w2_task    = (const float*)d_in[6];
    const float* b2_task    = (const float*)d_in[7];
    const float* w1_cls     = (const float*)d_in[8];
    const float* b1_cls     = (const float*)d_in[9];
    const float* w2_cls     = (const float*)d_in[10];
    const float* b2_cls     = (const float*)d_in[11];
    float* out = (float*)d_out;

    k1_partial<<<dim3(4, B_ * N_), C_>>>(feat_shot);
    k1_means_task<<<B_ * N_ + B_, C_>>>();
    k2_mlp1<<<H_ / 128, 256>>>(w1_task, b1_task, w1_cls, b1_cls);
    k2_mlp2<<<dim3(3, 12), 256>>>(w2_task, b2_task, w2_cls, b2_cls);
    k2c_shot<<<B_ * N_, C_>>>(feat_shot, x_shot);
    k3_pass1<<<dim3(98, B_), 256>>>(feat_query, feat_shot);
    k4_pass2<<<dim3(Q_, B_), 384>>>(feat_query, x_query, out);
}

// round 5
// speedup vs baseline: 1.2357x; 1.2357x over previous
#include <cuda_runtime.h>
#include <math.h>

#define DEV_INLINE __device__ __forceinline__

constexpr int B_ = 2, Q_ = 75, N_ = 5, T_ = 196, C_ = 384, H_ = 1536;
constexpr float TEMP_ = 10.0f;

// ---------------- scratch (device globals; no allocation) ----------------
__device__ float g_part[B_ * N_ * 4 * C_];      // partial t-sums of feat_shot
__device__ float g_mean_cls[B_ * N_ * C_];
__device__ float g_mean_task[B_ * C_];
__device__ float g_hidden[(B_ + B_ * N_) * H_]; // rows 0..1 task, 2..11 cls
__device__ float g_wt[B_ * C_];
__device__ float g_wc[B_ * N_ * C_];
__device__ float g_u[B_ * N_ * C_];             // wc * wt
__device__ float g_ns[B_ * N_ * T_];            // ||fs[b,n,t,:]||
__device__ float g_xsrw[B_ * N_ * C_];          // normalized reweighted shot vec
__device__ float g_xshat[B_ * N_ * C_];         // normalized x_shot
__device__ float g_num[B_ * Q_ * N_ * T_];      // fq . fs
__device__ float g_dq[B_ * Q_ * N_ * T_];       // fq . u  (map_q logits)
__device__ float g_nq[B_ * Q_ * T_];            // ||fq[b,q,t,:]||

// ---------------- reduction helpers ----------------
DEV_INLINE float blockReduceSum1(float v, float* red, int tid) {
    #pragma unroll
    for (int o = 16; o; o >>= 1) v += __shfl_xor_sync(0xffffffffu, v, o);
    int warp = tid >> 5, lane = tid & 31;
    int nw = blockDim.x >> 5;
    __syncthreads();
    if (lane == 0) red[warp] = v;
    __syncthreads();
    if (tid == 0) {
        float s = 0.f;
        for (int w = 0; w < nw; w++) s += red[w];
        red[0] = s;
    }
    __syncthreads();
    float r = red[0];
    __syncthreads();
    return r;
}

template <int NV>
DEV_INLINE void blockReduceSumArr(float* v, float* red, int tid) {
    #pragma unroll
    for (int i = 0; i < NV; i++)
        #pragma unroll
        for (int o = 16; o; o >>= 1) v[i] += __shfl_xor_sync(0xffffffffu, v[i], o);
    int warp = tid >> 5, lane = tid & 31;
    int nw = blockDim.x >> 5;
    __syncthreads();
    if (lane == 0)
        #pragma unroll
        for (int i = 0; i < NV; i++) red[warp * NV + i] = v[i];
    __syncthreads();
    if (tid == 0) {
        for (int w = 1; w < nw; w++)
            #pragma unroll
            for (int i = 0; i < NV; i++) red[i] += red[w * NV + i];
    }
    __syncthreads();
    #pragma unroll
    for (int i = 0; i < NV; i++) v[i] = red[i];
    __syncthreads();
}

template <int NV>
DEV_INLINE void blockReduceMaxArr(float* v, float* red, int tid) {
    #pragma unroll
    for (int i = 0; i < NV; i++)
        #pragma unroll
        for (int o = 16; o; o >>= 1) v[i] = fmaxf(v[i], __shfl_xor_sync(0xffffffffu, v[i], o));
    int warp = tid >> 5, lane = tid & 31;
    int nw = blockDim.x >> 5;
    __syncthreads();
    if (lane == 0)
        #pragma unroll
        for (int i = 0; i < NV; i++) red[warp * NV + i] = v[i];
    __syncthreads();
    if (tid == 0) {
        for (int w = 1; w < nw; w++)
            #pragma unroll
            for (int i = 0; i < NV; i++) red[i] = fmaxf(red[i], red[w * NV + i]);
    }
    __syncthreads();
    #pragma unroll
    for (int i = 0; i < NV; i++) v[i] = red[i];
    __syncthreads();
}

DEV_INLINE float sigmoidf(float x) { return 1.f / (1.f + expf(-x)); }

// ---------------- K1: feat_shot means ----------------
__global__ void k1_partial(const float* __restrict__ feat_shot) {
    int bn = blockIdx.y, chunk = blockIdx.x, c = threadIdx.x;
    const float* p = feat_shot + ((size_t)bn * T_ + chunk * 49) * C_ + c;
    float s = 0.f;
    #pragma unroll 7
    for (int t = 0; t < 49; t++) s += p[t * C_];
    g_part[(bn * 4 + chunk) * C_ + c] = s;
}

__global__ void k1_means_task() {
    int blk = blockIdx.x, c = threadIdx.x;
    if (blk < B_ * N_) {
        int bn = blk;
        float s = 0.f;
        #pragma unroll
        for (int k = 0; k < 4; k++) s += g_part[(bn * 4 + k) * C_ + c];
        g_mean_cls[bn * C_ + c] = s * (1.f / T_);
    } else {
        int b = blk - B_ * N_;
        float s = 0.f;
        #pragma unroll
        for (int n = 0; n < N_; n++) {
            float sn = 0.f;
            #pragma unroll
            for (int k = 0; k < 4; k++) sn += g_part[((b * N_ + n) * 4 + k) * C_ + c];
            s += sn * (1.f / T_);
        }
        g_mean_task[b * C_ + c] = s * (1.f / N_);
    }
}

// ---------------- K2: tiny MLPs (parallelism-first) ----------------
// layer 1: 12 rows x H outputs. grid = 48 blocks (32 j's each), 256 threads.
__global__ void __launch_bounds__(256) k2_mlp1(const float* __restrict__ w1t, const float* __restrict__ b1t,
                                               const float* __restrict__ w1c, const float* __restrict__ b1c) {
    __shared__ float xs[12 * C_];          // 18.4 KB
    __shared__ float part[8 * 12 * 32];    // 12.3 KB
    int tid = threadIdx.x;
    for (int i = tid; i < 12 * C_; i += 256) {
        int r = i / C_, c = i % C_;
        xs[i] = (r < B_) ? g_mean_task[r * C_ + c] : g_mean_cls[(r - B_) * C_ + c];
    }
    __syncthreads();
    int w = tid >> 5, l = tid & 31;
    int j = blockIdx.x * 32 + l;
    float acc[12];
    #pragma unroll
    for (int r = 0; r < 12; r++) acc[r] = 0.f;
    int c0 = w * 48;
    #pragma unroll 4
    for (int c = c0; c < c0 + 48; c++) {
        float wt = w1t[(size_t)c * H_ + j];
        float wc = w1c[(size_t)c * H_ + j];
        acc[0] += xs[0 * C_ + c] * wt;
        acc[1] += xs[1 * C_ + c] * wt;
        #pragma unroll
        for (int r = 2; r < 12; r++) acc[r] += xs[r * C_ + c] * wc;
    }
    #pragma unroll
    for (int r = 0; r < 12; r++) part[(w * 12 + r) * 32 + l] = acc[r];
    __syncthreads();
    for (int idx = tid; idx < 12 * 32; idx += 256) {
        int r = idx / 32, ll = idx % 32;
        float s = 0.f;
        #pragma unroll
        for (int ww = 0; ww < 8; ww++) s += part[(ww * 12 + r) * 32 + ll];
        int jj = blockIdx.x * 32 + ll;
        float bias = (r < B_) ? b1t[jj] : b1c[jj];
        g_hidden[r * H_ + jj] = fmaxf(s + bias, 0.f);
    }
}

// layer 2: grid (6 c-tiles, 12 rows) = 72 blocks, 256 threads (4 j-groups x 64 c).
__global__ void __launch_bounds__(256) k2_mlp2(const float* __restrict__ w2t, const float* __restrict__ b2t,
                                               const float* __restrict__ w2c, const float* __restrict__ b2c) {
    __shared__ float hid[H_];
    __shared__ float part[4 * 64];
    int row = blockIdx.y, ct = blockIdx.x, tid = threadIdx.x;
    for (int i = tid; i < H_; i += 256) hid[i] = g_hidden[row * H_ + i];
    __syncthreads();
    int jg = tid >> 6, cc = tid & 63;
    int c = ct * 64 + cc;
    const float* w2 = (row < B_) ? w2t : w2c;
    float a0 = 0.f, a1 = 0.f, a2 = 0.f, a3 = 0.f;
    int j0 = jg * 384;
    #pragma unroll 2
    for (int j = j0; j < j0 + 384; j += 4) {
        a0 += hid[j + 0] * w2[(size_t)(j + 0) * C_ + c];
        a1 += hid[j + 1] * w2[(size_t)(j + 1) * C_ + c];
        a2 += hid[j + 2] * w2[(size_t)(j + 2) * C_ + c];
        a3 += hid[j + 3] * w2[(size_t)(j + 3) * C_ + c];
    }
    part[jg * 64 + cc] = (a0 + a1) + (a2 + a3);
    __syncthreads();
    if (jg == 0) {
        float v = part[cc] + part[64 + cc] + part[128 + cc] + part[192 + cc];
        float bias = (row < B_) ? b2t[c] : b2c[c];
        v += bias;
        if (row < B_) g_wt[row * C_ + c] = v;
        else          g_wc[(row - B_) * C_ + c] = sigmoidf(v);
    }
}

// ---------------- K2c: shot-side (per b,n). 768 threads = 24 warps ----------------
// phase 1: per-t norms + map_s, t strided by 24 warps.
// phase 2: acc over t split into 2 halves of 98 across thread-halves, SMEM combine.
__global__ void __launch_bounds__(768) k2c_shot(const float* __restrict__ feat_shot,
                                                const float* __restrict__ x_shot) {
    __shared__ float u_s[C_];
    __shared__ float map_s[T_];
    __shared__ float red[32];
    __shared__ float half_part[C_];
    int bn = blockIdx.x, b = bn / N_, tid = threadIdx.x;
    int warp = tid >> 5, lane = tid & 31;
    if (tid < C_) {
        float uval = g_wc[bn * C_ + tid] * g_wt[b * C_ + tid];
        g_u[bn * C_ + tid] = uval;
        u_s[tid] = uval;
    }
    __syncthreads();
    const float* fsr = feat_shot + (size_t)bn * T_ * C_;
    for (int t = warp; t < T_; t += 24) {
        float ss = 0.f, du = 0.f;
        for (int c = lane; c < C_; c += 32) {
            float f = fsr[t * C_ + c];
            ss += f * f;
            du += f * u_s[c];
        }
        #pragma unroll
        for (int o = 16; o; o >>= 1) {
            ss += __shfl_xor_sync(0xffffffffu, ss, o);
            du += __shfl_xor_sync(0xffffffffu, du, o);
        }
        if (lane == 0) {
            g_ns[bn * T_ + t] = sqrtf(ss);
            map_s[t] = sigmoidf(du);
        }
    }
    __syncthreads();
    // phase 2: thread (h, c) sums t in [h*98, h*98+98)
    int h = tid / C_, c = tid % C_;
    float a = 0.f;
    {
        int t0 = h * 98;
        const float* p = fsr + (size_t)t0 * C_ + c;
        #pragma unroll 7
        for (int t = 0; t < 98; t++) a += p[(size_t)t * C_] * map_s[t0 + t];
    }
    if (h == 1) half_part[c] = a;
    __syncthreads();
    float v = 0.f;
    if (h == 0) {
        a += half_part[c];
        v = g_wc[bn * C_ + c] * a * (1.f / T_);
    }
    float s2 = blockReduceSum1(v * v, red, tid);
    if (h == 0) g_xsrw[bn * C_ + c] = v / (1e-16f + sqrtf(s2));
    float xv = (h == 0) ? x_shot[(size_t)bn * C_ + c] : 0.f;
    float xn2 = blockReduceSum1(xv * xv, red, tid);
    if (h == 0) g_xshat[bn * C_ + c] = xv / fmaxf(sqrtf(xn2), 1e-12f);
}

// ---------------- K3: pass 1 — num, dq, nq (streams feat_query once) ----------------
__global__ void __launch_bounds__(256) k3_pass1(const float* __restrict__ feat_query,
                                                const float* __restrict__ feat_shot) {
    __shared__ float fs_s[2 * N_ * C_];
    __shared__ float u_s[N_ * C_];
    int b = blockIdx.y, t0 = blockIdx.x * 2, tid = threadIdx.x;
    for (int i = tid; i < 2 * N_ * C_; i += 256) {
        int tt = i / (N_ * C_), r = i % (N_ * C_);
        int n = r / C_, c = r % C_;
        fs_s[i] = feat_shot[((size_t)(b * N_ + n) * T_ + t0 + tt) * C_ + c];
    }
    for (int i = tid; i < N_ * C_; i += 256) u_s[i] = g_u[b * N_ * C_ + i];
    __syncthreads();

    int warp = tid >> 5, lane = tid & 31;
    for (int task = warp; task < 38; task += 8) {
        int tt = task / 19, qi = task % 19;
        int t = t0 + tt, q0 = qi * 4;

        float4 fq[4][3];
        #pragma unroll
        for (int qq = 0; qq < 4; qq++) {
            int q = q0 + qq;
            if (q < Q_) {
                const float* p = feat_query + (((size_t)(b * Q_ + q)) * T_ + t) * C_;
                #pragma unroll
                for (int j = 0; j < 3; j++)
                    fq[qq][j] = *(const float4*)(p + 4 * (lane + 32 * j));
            } else {
                #pragma unroll
                for (int j = 0; j < 3; j++) fq[qq][j] = make_float4(0.f, 0.f, 0.f, 0.f);
            }
        }

        float acc[44];
        #pragma unroll
        for (int i = 0; i < 44; i++) acc[i] = 0.f;

        #pragma unroll
        for (int j = 0; j < 3; j++) {
            int cb = 4 * (lane + 32 * j);
            #pragma unroll
            for (int n = 0; n < N_; n++) {
                float4 s4 = *(const float4*)&fs_s[(tt * N_ + n) * C_ + cb];
                float4 u4 = *(const float4*)&u_s[n * C_ + cb];
                #pragma unroll
                for (int qq = 0; qq < 4; qq++) {
                    float4 f = fq[qq][j];
                    acc[qq * 5 + n]      += f.x * s4.x + f.y * s4.y + f.z * s4.z + f.w * s4.w;
                    acc[20 + qq * 5 + n] += f.x * u4.x + f.y * u4.y + f.z * u4.z + f.w * u4.w;
                }
            }
            #pragma unroll
            for (int qq = 0; qq < 4; qq++) {
                float4 f = fq[qq][j];
                acc[40 + qq] += f.x * f.x + f.y * f.y + f.z * f.z + f.w * f.w;
            }
        }

        #pragma unroll
        for (int i = 0; i < 44; i++)
            #pragma unroll
            for (int o = 16; o; o >>= 1) acc[i] += __shfl_xor_sync(0xffffffffu, acc[i], o);

        if (lane == 0) {
            #pragma unroll
            for (int qq = 0; qq < 4; qq++) {
                int q = q0 + qq;
                if (q < Q_) {
                    size_t base = (size_t)(b * Q_ + q) * N_ * T_;
                    #pragma unroll
                    for (int n = 0; n < N_; n++) {
                        g_num[base + n * T_ + t] = acc[qq * 5 + n];
                        g_dq[base + n * T_ + t]  = acc[20 + qq * 5 + n];
                    }
                    g_nq[(b * Q_ + q) * T_ + t] = sqrtf(acc[40 + qq]);
                }
            }
        }
    }
}

// ---------------- K4: pass 2 — per (b,q): sim/max, acc GEMM, all outputs ----------------
__global__ void __launch_bounds__(384) k4_pass2(const float* __restrict__ feat_query,
                                                const float* __restrict__ x_query,
                                                float* __restrict__ out) {
    __shared__ float map_s[N_ * T_];
    __shared__ float4 part4[4 * N_ * 96];
    __shared__ float accf[N_ * C_];
    __shared__ float red[128];

    int q = blockIdx.x, b = blockIdx.y, tid = threadIdx.x;
    int bq = b * Q_ + q;
    size_t nt_base = (size_t)bq * N_ * T_;

    float mx[N_];
    #pragma unroll
    for (int n = 0; n < N_; n++) mx[n] = -1e30f;
    if (tid < T_) {
        float nqv = g_nq[bq * T_ + tid];
        #pragma unroll
        for (int n = 0; n < N_; n++) {
            float denom = fmaxf(nqv * g_ns[(b * N_ + n) * T_ + tid], 1e-8f);
            mx[n] = g_num[nt_base + n * T_ + tid] / denom;
        }
    }
    blockReduceMaxArr<N_>(mx, red, tid);
    if (tid == 0) {
        float lg = (mx[0] + mx[1] + mx[2] + mx[3] + mx[4]) * (1.f / N_);
        out[bq] = lg;
        out[B_ * Q_ + bq] = lg;
    }

    for (int i = tid; i < N_ * T_; i += 384) map_s[i] = sigmoidf(g_dq[nt_base + i]);
    __syncthreads();

    int g = tid / 96, cg = tid % 96;
    float4 acc[N_];
    #pragma unroll
    for (int n = 0; n < N_; n++) acc[n] = make_float4(0.f, 0.f, 0.f, 0.f);
    const float* fqp = feat_query + ((size_t)bq * T_ + g * 49) * C_ + 4 * cg;
    for (int t = 0; t < 49; t++) {
        float4 f = *(const float4*)(fqp + (size_t)t * C_);
        int tg = g * 49 + t;
        #pragma unroll
        for (int n = 0; n < N_; n++) {
            float m = map_s[n * T_ + tg];
            acc[n].x += f.x * m; acc[n].y += f.y * m;
            acc[n].z += f.z * m; acc[n].w += f.w * m;
        }
    }
    #pragma unroll
    for (int n = 0; n < N_; n++) part4[(g * N_ + n) * 96 + cg] = acc[n];
    __syncthreads();
    for (int idx = tid; idx < N_ * 96; idx += 384) {
        int n = idx / 96, c4 = idx % 96;
        float4 s0 = part4[(0 * N_ + n) * 96 + c4];
        float4 s1 = part4[(1 * N_ + n) * 96 + c4];
        float4 s2 = part4[(2 * N_ + n) * 96 + c4];
        float4 s3 = part4[(3 * N_ + n) * 96 + c4];
        float4 s;
        s.x = s0.x + s1.x + s2.x + s3.x;
        s.y = s0.y + s1.y + s2.y + s3.y;
        s.z = s0.z + s1.z + s2.z + s3.z;
        s.w = s0.w + s1.w + s2.w + s3.w;
        *(float4*)&accf[n * C_ + 4 * c4] = s;
    }
    __syncthreads();

    int c = tid;
    #pragma unroll
    for (int n = 0; n < N_; n++) {
        float v = g_wc[(b * N_ + n) * C_ + c] * accf[n * C_ + c] * (1.f / T_);
        float pr[2] = { v * v, v * g_xsrw[(b * N_ + n) * C_ + c] };
        blockReduceSumArr<2>(pr, red, tid);
        if (tid == 0)
            out[2 * B_ * Q_ + B_ * Q_ * N_ + bq * N_ + n] = pr[1] / (1e-16f + sqrtf(pr[0]));
    }

    float xv = x_query[(size_t)bq * C_ + c];
    float pr6[6];
    pr6[0] = xv * xv;
    #pragma unroll
    for (int n = 0; n < N_; n++) pr6[1 + n] = xv * g_xshat[(b * N_ + n) * C_ + c];
    blockReduceSumArr<6>(pr6, red, tid);
    if (tid == 0) {
        float qn = fmaxf(sqrtf(pr6[0]), 1e-12f);
        #pragma unroll
        for (int n = 0; n < N_; n++)
            out[2 * B_ * Q_ + bq * N_ + n] = TEMP_ * pr6[1 + n] / qn;
    }
}

// ---------------- launch ----------------
extern "C" void kernel_launch(void* const* d_in, const int* in_sizes, int n_in,
                              void* d_out, int out_size) {
    const float* feat_shot  = (const float*)d_in[0];
    const float* feat_query = (const float*)d_in[1];
    const float* x_shot     = (const float*)d_in[2];
    const float* x_query    = (const float*)d_in[3];
    const float* w1_task    = (const float*)d_in[4];
    const float* b1_task    = (const float*)d_in[5];
    const float* w2_task    = (const float*)d_in[6];
    const float* b2_task    = (const float*)d_in[7];
    const float* w1_cls     = (const float*)d_in[8];
    const float* b1_cls     = (const float*)d_in[9];
    const float* w2_cls     = (const float*)d_in[10];
    const float* b2_cls     = (const float*)d_in[11];
    float* out = (float*)d_out;

    k1_partial<<<dim3(4, B_ * N_), C_>>>(feat_shot);
    k1_means_task<<<B_ * N_ + B_, C_>>>();
    k2_mlp1<<<H_ / 32, 256>>>(w1_task, b1_task, w1_cls, b1_cls);
    k2_mlp2<<<dim3(C_ / 64, 12), 256>>>(w2_task, b2_task, w2_cls, b2_cls);
    k2c_shot<<<B_ * N_, 768>>>(feat_shot, x_shot);
    k3_pass1<<<dim3(98, B_), 256>>>(feat_query, feat_shot);
    k4_pass2<<<dim3(Q_, B_), 384>>>(feat_query, x_query, out);
}

// round 10
// speedup vs baseline: 1.3663x; 1.1057x over previous
#include <cuda_runtime.h>
#include <math.h>

#define DEV_INLINE __device__ __forceinline__

constexpr int B_ = 2, Q_ = 75, N_ = 5, T_ = 196, C_ = 384, H_ = 1536;
constexpr float TEMP_ = 10.0f;
constexpr int TCH_ = 14;                  // t-chunks for k1 (14*14=196)
constexpr int JCH_ = 8;                   // j-chunks for mlp2 (8*192=1536)

// ---------------- scratch (device globals; no allocation) ----------------
__device__ float g_part[B_ * N_ * TCH_ * C_];
__device__ float g_mean_cls[B_ * N_ * C_];
__device__ float g_mean_task[B_ * C_];
__device__ float g_hidden[(B_ + B_ * N_) * H_]; // rows 0..1 task, 2..11 cls
__device__ float g_p2[JCH_ * 12 * C_];          // mlp2 partials [jchunk][row][c]
__device__ float g_wt[B_ * C_];
__device__ float g_wc[B_ * N_ * C_];
__device__ float g_u[B_ * N_ * C_];
__device__ float g_ns[B_ * N_ * T_];
__device__ float g_xsrw[B_ * N_ * C_];
__device__ float g_xshat[B_ * N_ * C_];
__device__ float g_num[B_ * Q_ * N_ * T_];
__device__ float g_dq[B_ * Q_ * N_ * T_];
__device__ float g_nq[B_ * Q_ * T_];

// ---------------- reduction helpers ----------------
DEV_INLINE float blockReduceSum1(float v, float* red, int tid) {
    #pragma unroll
    for (int o = 16; o; o >>= 1) v += __shfl_xor_sync(0xffffffffu, v, o);
    int warp = tid >> 5, lane = tid & 31;
    int nw = blockDim.x >> 5;
    __syncthreads();
    if (lane == 0) red[warp] = v;
    __syncthreads();
    if (tid == 0) {
        float s = 0.f;
        for (int w = 0; w < nw; w++) s += red[w];
        red[0] = s;
    }
    __syncthreads();
    float r = red[0];
    __syncthreads();
    return r;
}

template <int NV>
DEV_INLINE void blockReduceSumArr(float* v, float* red, int tid) {
    #pragma unroll
    for (int i = 0; i < NV; i++)
        #pragma unroll
        for (int o = 16; o; o >>= 1) v[i] += __shfl_xor_sync(0xffffffffu, v[i], o);
    int warp = tid >> 5, lane = tid & 31;
    int nw = blockDim.x >> 5;
    __syncthreads();
    if (lane == 0)
        #pragma unroll
        for (int i = 0; i < NV; i++) red[warp * NV + i] = v[i];
    __syncthreads();
    if (tid == 0) {
        for (int w = 1; w < nw; w++)
            #pragma unroll
            for (int i = 0; i < NV; i++) red[i] += red[w * NV + i];
    }
    __syncthreads();
    #pragma unroll
    for (int i = 0; i < NV; i++) v[i] = red[i];
    __syncthreads();
}

template <int NV>
DEV_INLINE void blockReduceMaxArr(float* v, float* red, int tid) {
    #pragma unroll
    for (int i = 0; i < NV; i++)
        #pragma unroll
        for (int o = 16; o; o >>= 1) v[i] = fmaxf(v[i], __shfl_xor_sync(0xffffffffu, v[i], o));
    int warp = tid >> 5, lane = tid & 31;
    int nw = blockDim.x >> 5;
    __syncthreads();
    if (lane == 0)
        #pragma unroll
        for (int i = 0; i < NV; i++) red[warp * NV + i] = v[i];
    __syncthreads();
    if (tid == 0) {
        for (int w = 1; w < nw; w++)
            #pragma unroll
            for (int i = 0; i < NV; i++) red[i] = fmaxf(red[i], red[w * NV + i]);
    }
    __syncthreads();
    #pragma unroll
    for (int i = 0; i < NV; i++) v[i] = red[i];
    __syncthreads();
}

DEV_INLINE float sigmoidf(float x) { return 1.f / (1.f + expf(-x)); }

// ---------------- K1: feat_shot partial sums ----------------
__global__ void k1_partial(const float* __restrict__ feat_shot) {
    int bn = blockIdx.y, chunk = blockIdx.x, c = threadIdx.x;
    const float* p = feat_shot + ((size_t)bn * T_ + chunk * 14) * C_ + c;
    float s0 = 0.f, s1 = 0.f;
    #pragma unroll
    for (int t = 0; t < 14; t += 2) {
        s0 += p[(size_t)t * C_];
        s1 += p[(size_t)(t + 1) * C_];
    }
    g_part[(bn * TCH_ + chunk) * C_ + c] = s0 + s1;
}

__global__ void k1_means_task() {
    int blk = blockIdx.x, c = threadIdx.x;
    if (blk < B_ * N_) {
        int bn = blk;
        const float* p = g_part + bn * TCH_ * C_ + c;
        float a0 = 0.f, a1 = 0.f;
        #pragma unroll
        for (int k = 0; k < TCH_; k += 2) {
            a0 += p[(size_t)k * C_];
            a1 += p[(size_t)(k + 1) * C_];
        }
        g_mean_cls[bn * C_ + c] = (a0 + a1) * (1.f / T_);
    } else {
        int b = blk - B_ * N_;
        const float* p = g_part + b * N_ * TCH_ * C_ + c;
        float a0 = 0.f, a1 = 0.f, a2 = 0.f, a3 = 0.f;
        #pragma unroll 2
        for (int i = 0; i < N_ * TCH_ - 2; i += 4) {
            a0 += p[(size_t)(i + 0) * C_];
            a1 += p[(size_t)(i + 1) * C_];
            a2 += p[(size_t)(i + 2) * C_];
            a3 += p[(size_t)(i + 3) * C_];
        }
        a0 += p[(size_t)68 * C_];
        a1 += p[(size_t)69 * C_];
        g_mean_task[b * C_ + c] = ((a0 + a1) + (a2 + a3)) * (1.f / T_) * (1.f / N_);
    }
}

// ---------------- K2 layer 1 ----------------
__global__ void __launch_bounds__(256) k2_mlp1(const float* __restrict__ w1t, const float* __restrict__ b1t,
                                               const float* __restrict__ w1c, const float* __restrict__ b1c) {
    __shared__ float xs[12 * C_];
    __shared__ float part[8 * 12 * 32];
    int tid = threadIdx.x;
    for (int i = tid; i < 12 * C_; i += 256) {
        int r = i / C_, c = i % C_;
        xs[i] = (r < B_) ? g_mean_task[r * C_ + c] : g_mean_cls[(r - B_) * C_ + c];
    }
    __syncthreads();
    int w = tid >> 5, l = tid & 31;
    int j = blockIdx.x * 32 + l;
    float acc[12];
    #pragma unroll
    for (int r = 0; r < 12; r++) acc[r] = 0.f;
    int c0 = w * 48;
    float nwt = w1t[(size_t)c0 * H_ + j];
    float nwc = w1c[(size_t)c0 * H_ + j];
    for (int c = c0; c < c0 + 48; c++) {
        float wt = nwt, wc = nwc;
        if (c + 1 < c0 + 48) {
            nwt = w1t[(size_t)(c + 1) * H_ + j];
            nwc = w1c[(size_t)(c + 1) * H_ + j];
        }
        acc[0] += xs[0 * C_ + c] * wt;
        acc[1] += xs[1 * C_ + c] * wt;
        #pragma unroll
        for (int r = 2; r < 12; r++) acc[r] += xs[r * C_ + c] * wc;
    }
    #pragma unroll
    for (int r = 0; r < 12; r++) part[(w * 12 + r) * 32 + l] = acc[r];
    __syncthreads();
    for (int idx = tid; idx < 12 * 32; idx += 256) {
        int r = idx / 32, ll = idx % 32;
        float s = 0.f;
        #pragma unroll
        for (int ww = 0; ww < 8; ww++) s += part[(ww * 12 + r) * 32 + ll];
        int jj = blockIdx.x * 32 + ll;
        float bias = (r < B_) ? b1t[jj] : b1c[jj];
        g_hidden[r * H_ + jj] = fmaxf(s + bias, 0.f);
    }
}

// ---------------- K2 layer 2, stage A ----------------
__global__ void __launch_bounds__(512) k2_mlp2A(const float* __restrict__ w2t,
                                                const float* __restrict__ w2c) {
    __shared__ float hid_s[192];
    __shared__ float4 part4[16][32];
    int ct = blockIdx.x, row = blockIdx.y, z = blockIdx.z;
    int tid = threadIdx.x;
    if (tid < 192) hid_s[tid] = g_hidden[row * H_ + z * 192 + tid];
    __syncthreads();
    int jg = tid >> 5, q = tid & 31;
    int cbase = ct * 128 + q * 4;
    const float* w2 = (row < B_) ? w2t : w2c;
    int jl0 = jg * 12;
    const float* wp = w2 + (size_t)(z * 192 + jl0) * C_ + cbase;

    float4 a = make_float4(0.f, 0.f, 0.f, 0.f);
    float4 nf = *(const float4*)wp;
    #pragma unroll
    for (int jj = 0; jj < 12; jj++) {
        float4 f = nf;
        if (jj + 1 < 12) nf = *(const float4*)(wp + (size_t)(jj + 1) * C_);
        float m = hid_s[jl0 + jj];
        a.x += f.x * m; a.y += f.y * m; a.z += f.z * m; a.w += f.w * m;
    }
    part4[jg][q] = a;
    __syncthreads();
    if (tid < 32) {
        float4 s = part4[0][tid];
        #pragma unroll
        for (int g = 1; g < 16; g++) {
            float4 t = part4[g][tid];
            s.x += t.x; s.y += t.y; s.z += t.z; s.w += t.w;
        }
        *(float4*)&g_p2[(size_t)(z * 12 + row) * C_ + ct * 128 + tid * 4] = s;
    }
}

__global__ void k2_mlp2B(const float* __restrict__ b2t, const float* __restrict__ b2c) {
    int row = blockIdx.x, c = threadIdx.x;
    float a0 = 0.f, a1 = 0.f, a2 = 0.f, a3 = 0.f;
    #pragma unroll
    for (int z = 0; z < JCH_; z += 4) {
        a0 += g_p2[(size_t)((z + 0) * 12 + row) * C_ + c];
        a1 += g_p2[(size_t)((z + 1) * 12 + row) * C_ + c];
        a2 += g_p2[(size_t)((z + 2) * 12 + row) * C_ + c];
        a3 += g_p2[(size_t)((z + 3) * 12 + row) * C_ + c];
    }
    float v = (a0 + a1) + (a2 + a3);
    if (row < B_) g_wt[row * C_ + c] = v + b2t[c];
    else          g_wc[(row - B_) * C_ + c] = sigmoidf(v + b2c[c]);
}

// ---------------- K2c: shot-side ----------------
__global__ void __launch_bounds__(768) k2c_shot(const float* __restrict__ feat_shot,
                                                const float* __restrict__ x_shot) {
    __shared__ float u_s[C_];
    __shared__ float map_s[T_];
    __shared__ float red[32];
    __shared__ float4 part4[8][96];
    int bn = blockIdx.x, b = bn / N_, tid = threadIdx.x;
    int warp = tid >> 5, lane = tid & 31;
    if (tid < C_) {
        float uval = g_wc[bn * C_ + tid] * g_wt[b * C_ + tid];
        g_u[bn * C_ + tid] = uval;
        u_s[tid] = uval;
    }
    __syncthreads();
    const float* fsr = feat_shot + (size_t)bn * T_ * C_;
    for (int t = warp; t < T_; t += 24) {
        float ss = 0.f, du = 0.f;
        for (int c = lane; c < C_; c += 32) {
            float f = fsr[t * C_ + c];
            ss += f * f;
            du += f * u_s[c];
        }
        #pragma unroll
        for (int o = 16; o; o >>= 1) {
            ss += __shfl_xor_sync(0xffffffffu, ss, o);
            du += __shfl_xor_sync(0xffffffffu, du, o);
        }
        if (lane == 0) {
            g_ns[bn * T_ + t] = sqrtf(ss);
            map_s[t] = sigmoidf(du);
        }
    }
    __syncthreads();
    int tg = tid / 96, q = tid % 96;
    int start = (tg < 4) ? tg * 25 : 100 + (tg - 4) * 24;
    int len = (tg < 4) ? 25 : 24;
    int cbase = q * 4;
    const float* p = fsr + (size_t)start * C_ + cbase;
    float4 a = make_float4(0.f, 0.f, 0.f, 0.f);
    float4 nf = *(const float4*)p;
    for (int i = 0; i < len; i++) {
        float4 f = nf;
        if (i + 1 < len) nf = *(const float4*)(p + (size_t)(i + 1) * C_);
        float m = map_s[start + i];
        a.x += f.x * m; a.y += f.y * m; a.z += f.z * m; a.w += f.w * m;
    }
    part4[tg][q] = a;
    __syncthreads();
    float4 v4 = make_float4(0.f, 0.f, 0.f, 0.f);
    float loc = 0.f;
    if (tid < 96) {
        float4 s = part4[0][tid];
        #pragma unroll
        for (int g = 1; g < 8; g++) {
            float4 t = part4[g][tid];
            s.x += t.x; s.y += t.y; s.z += t.z; s.w += t.w;
        }
        float4 wc4 = *(const float4*)&g_wc[bn * C_ + tid * 4];
        v4.x = wc4.x * s.x * (1.f / T_);
        v4.y = wc4.y * s.y * (1.f / T_);
        v4.z = wc4.z * s.z * (1.f / T_);
        v4.w = wc4.w * s.w * (1.f / T_);
        loc = v4.x * v4.x + v4.y * v4.y + v4.z * v4.z + v4.w * v4.w;
    }
    float s2 = blockReduceSum1(loc, red, tid);
    if (tid < 96) {
        float inv = 1.f / (1e-16f + sqrtf(s2));
        float4 o = make_float4(v4.x * inv, v4.y * inv, v4.z * inv, v4.w * inv);
        *(float4*)&g_xsrw[bn * C_ + tid * 4] = o;
    }
    float4 xq4 = make_float4(0.f, 0.f, 0.f, 0.f);
    float loc2 = 0.f;
    if (tid < 96) {
        xq4 = *(const float4*)&x_shot[(size_t)bn * C_ + tid * 4];
        loc2 = xq4.x * xq4.x + xq4.y * xq4.y + xq4.z * xq4.z + xq4.w * xq4.w;
    }
    float n2 = blockReduceSum1(loc2, red, tid);
    if (tid < 96) {
        float inv = 1.f / fmaxf(sqrtf(n2), 1e-12f);
        float4 o = make_float4(xq4.x * inv, xq4.y * inv, xq4.z * inv, xq4.w * inv);
        *(float4*)&g_xshat[bn * C_ + tid * 4] = o;
    }
}

// ---------------- K3: pass 1 ----------------
__global__ void __launch_bounds__(256) k3_pass1(const float* __restrict__ feat_query,
                                                const float* __restrict__ feat_shot) {
    __shared__ float fs_s[2 * N_ * C_];
    __shared__ float u_s[N_ * C_];
    int b = blockIdx.y, t0 = blockIdx.x * 2, tid = threadIdx.x;
    for (int i = tid; i < 2 * N_ * C_; i += 256) {
        int tt = i / (N_ * C_), r = i % (N_ * C_);
        int n = r / C_, c = r % C_;
        fs_s[i] = feat_shot[((size_t)(b * N_ + n) * T_ + t0 + tt) * C_ + c];
    }
    for (int i = tid; i < N_ * C_; i += 256) u_s[i] = g_u[b * N_ * C_ + i];
    __syncthreads();

    int warp = tid >> 5, lane = tid & 31;
    for (int task = warp; task < 38; task += 8) {
        int tt = task / 19, qi = task % 19;
        int t = t0 + tt, q0 = qi * 4;

        float4 fq[4][3];
        #pragma unroll
        for (int qq = 0; qq < 4; qq++) {
            int q = q0 + qq;
            if (q < Q_) {
                const float* p = feat_query + (((size_t)(b * Q_ + q)) * T_ + t) * C_;
                #pragma unroll
                for (int j = 0; j < 3; j++)
                    fq[qq][j] = *(const float4*)(p + 4 * (lane + 32 * j));
            } else {
                #pragma unroll
                for (int j = 0; j < 3; j++) fq[qq][j] = make_float4(0.f, 0.f, 0.f, 0.f);
            }
        }

        float acc[44];
        #pragma unroll
        for (int i = 0; i < 44; i++) acc[i] = 0.f;

        #pragma unroll
        for (int j = 0; j < 3; j++) {
            int cb = 4 * (lane + 32 * j);
            #pragma unroll
            for (int n = 0; n < N_; n++) {
                float4 s4 = *(const float4*)&fs_s[(tt * N_ + n) * C_ + cb];
                float4 u4 = *(const float4*)&u_s[n * C_ + cb];
                #pragma unroll
                for (int qq = 0; qq < 4; qq++) {
                    float4 f = fq[qq][j];
                    acc[qq * 5 + n]      += f.x * s4.x + f.y * s4.y + f.z * s4.z + f.w * s4.w;
                    acc[20 + qq * 5 + n] += f.x * u4.x + f.y * u4.y + f.z * u4.z + f.w * u4.w;
                }
            }
            #pragma unroll
            for (int qq = 0; qq < 4; qq++) {
                float4 f = fq[qq][j];
                acc[40 + qq] += f.x * f.x + f.y * f.y + f.z * f.z + f.w * f.w;
            }
        }

        #pragma unroll
        for (int i = 0; i < 44; i++)
            #pragma unroll
            for (int o = 16; o; o >>= 1) acc[i] += __shfl_xor_sync(0xffffffffu, acc[i], o);

        if (lane == 0) {
            #pragma unroll
            for (int qq = 0; qq < 4; qq++) {
                int q = q0 + qq;
                if (q < Q_) {
                    size_t base = (size_t)(b * Q_ + q) * N_ * T_;
                    #pragma unroll
                    for (int n = 0; n < N_; n++) {
                        g_num[base + n * T_ + t] = acc[qq * 5 + n];
                        g_dq[base + n * T_ + t]  = acc[20 + qq * 5 + n];
                    }
                    g_nq[(b * Q_ + q) * T_ + t] = sqrtf(acc[40 + qq]);
                }
            }
        }
    }
}

// ---------------- K4: pass 2 ----------------
__global__ void __launch_bounds__(384) k4_pass2(const float* __restrict__ feat_query,
                                                const float* __restrict__ x_query,
                                                float* __restrict__ out) {
    __shared__ float map_s[N_ * T_];
    __shared__ float4 part4[4 * N_ * 96];
    __shared__ float accf[N_ * C_];
    __shared__ float red[128];

    int q = blockIdx.x, b = blockIdx.y, tid = threadIdx.x;
    int bq = b * Q_ + q;
    size_t nt_base = (size_t)bq * N_ * T_;

    float mx[N_];
    #pragma unroll
    for (int n = 0; n < N_; n++) mx[n] = -1e30f;
    if (tid < T_) {
        float nqv = g_nq[bq * T_ + tid];
        #pragma unroll
        for (int n = 0; n < N_; n++) {
            float denom = fmaxf(nqv * g_ns[(b * N_ + n) * T_ + tid], 1e-8f);
            mx[n] = g_num[nt_base + n * T_ + tid] / denom;
        }
    }
    blockReduceMaxArr<N_>(mx, red, tid);
    if (tid == 0) {
        float lg = (mx[0] + mx[1] + mx[2] + mx[3] + mx[4]) * (1.f / N_);
        out[bq] = lg;
        out[B_ * Q_ + bq] = lg;
    }

    for (int i = tid; i < N_ * T_; i += 384) map_s[i] = sigmoidf(g_dq[nt_base + i]);
    __syncthreads();

    int g = tid / 96, cg = tid % 96;
    float4 acc[N_];
    #pragma unroll
    for (int n = 0; n < N_; n++) acc[n] = make_float4(0.f, 0.f, 0.f, 0.f);
    const float* fqp = feat_query + ((size_t)bq * T_ + g * 49) * C_ + 4 * cg;
    float4 nf = *(const float4*)fqp;
    for (int t = 0; t < 49; t++) {
        float4 f = nf;
        if (t + 1 < 49) nf = *(const float4*)(fqp + (size_t)(t + 1) * C_);
        int tg = g * 49 + t;
        #pragma unroll
        for (int n = 0; n < N_; n++) {
            float m = map_s[n * T_ + tg];
            acc[n].x += f.x * m; acc[n].y += f.y * m;
            acc[n].z += f.z * m; acc[n].w += f.w * m;
        }
    }
    #pragma unroll
    for (int n = 0; n < N_; n++) part4[(g * N_ + n) * 96 + cg] = acc[n];
    __syncthreads();
    for (int idx = tid; idx < N_ * 96; idx += 384) {
        int n = idx / 96, c4 = idx % 96;
        float4 s0 = part4[(0 * N_ + n) * 96 + c4];
        float4 s1 = part4[(1 * N_ + n) * 96 + c4];
        float4 s2 = part4[(2 * N_ + n) * 96 + c4];
        float4 s3 = part4[(3 * N_ + n) * 96 + c4];
        float4 s;
        s.x = s0.x + s1.x + s2.x + s3.x;
        s.y = s0.y + s1.y + s2.y + s3.y;
        s.z = s0.z + s1.z + s2.z + s3.z;
        s.w = s0.w + s1.w + s2.w + s3.w;
        *(float4*)&accf[n * C_ + 4 * c4] = s;
    }
    __syncthreads();

    int c = tid;
    #pragma unroll
    for (int n = 0; n < N_; n++) {
        float v = g_wc[(b * N_ + n) * C_ + c] * accf[n * C_ + c] * (1.f / T_);
        float pr[2] = { v * v, v * g_xsrw[(b * N_ + n) * C_ + c] };
        blockReduceSumArr<2>(pr, red, tid);
        if (tid == 0)
            out[2 * B_ * Q_ + B_ * Q_ * N_ + bq * N_ + n] = pr[1] / (1e-16f + sqrtf(pr[0]));
    }

    float xv = x_query[(size_t)bq * C_ + c];
    float pr6[6];
    pr6[0] = xv * xv;
    #pragma unroll
    for (int n = 0; n < N_; n++) pr6[1 + n] = xv * g_xshat[(b * N_ + n) * C_ + c];
    blockReduceSumArr<6>(pr6, red, tid);
    if (tid == 0) {
        float qn = fmaxf(sqrtf(pr6[0]), 1e-12f);
        #pragma unroll
        for (int n = 0; n < N_; n++)
            out[2 * B_ * Q_ + bq * N_ + n] = TEMP_ * pr6[1 + n] / qn;
    }
}

// ---------------- launch ----------------
extern "C" void kernel_launch(void* const* d_in, const int* in_sizes, int n_in,
                              void* d_out, int out_size) {
    const float* feat_shot  = (const float*)d_in[0];
    const float* feat_query = (const float*)d_in[1];
    const float* x_shot     = (const float*)d_in[2];
    const float* x_query    = (const float*)d_in[3];
    const float* w1_task    = (const float*)d_in[4];
    const float* b1_task    = (const float*)d_in[5];
    const float* w2_task    = (const float*)d_in[6];
    const float* b2_task    = (const float*)d_in[7];
    const float* w1_cls     = (const float*)d_in[8];
    const float* b1_cls     = (const float*)d_in[9];
    const float* w2_cls     = (const float*)d_in[10];
    const float* b2_cls     = (const float*)d_in[11];
    float* out = (float*)d_out;

    k1_partial<<<dim3(TCH_, B_ * N_), C_>>>(feat_shot);
    k1_means_task<<<B_ * N_ + B_, C_>>>();
    k2_mlp1<<<H_ / 32, 256>>>(w1_task, b1_task, w1_cls, b1_cls);
    k2_mlp2A<<<dim3(3, 12, JCH_), 512>>>(w2_task, w2_cls);
    k2_mlp2B<<<12, C_>>>(b2_task, b2_cls);
    k2c_shot<<<B_ * N_, 768>>>(feat_shot, x_shot);
    k3_pass1<<<dim3(98, B_), 256>>>(feat_query, feat_shot);
    k4_pass2<<<dim3(Q_, B_), 384>>>(feat_query, x_query, out);
}

// round 12
// speedup vs baseline: 1.4403x; 1.0541x over previous
#include <cuda_runtime.h>
#include <math.h>

#define DEV_INLINE __device__ __forceinline__

constexpr int B_ = 2, Q_ = 75, N_ = 5, T_ = 196, C_ = 384, H_ = 1536;
constexpr float TEMP_ = 10.0f;
constexpr int TCH_ = 14;                  // t-chunks for k1 (14*14=196)
constexpr int JCH_ = 8;                   // j-chunks for mlp2 (8*192=1536)

// ---------------- scratch (device globals; no allocation) ----------------
__device__ float g_part[B_ * N_ * TCH_ * C_];
__device__ float g_hidden[(B_ + B_ * N_) * H_]; // rows 0..1 task, 2..11 cls
__device__ float g_p2[JCH_ * 12 * C_];          // mlp2 partials [jchunk][row][c]
__device__ float g_wc[B_ * N_ * C_];
__device__ float g_u[B_ * N_ * C_];
__device__ float g_ns[B_ * N_ * T_];
__device__ float g_xsrw[B_ * N_ * C_];
__device__ float g_xshat[B_ * N_ * C_];
__device__ float g_num[B_ * Q_ * N_ * T_];
__device__ float g_dq[B_ * Q_ * N_ * T_];
__device__ float g_nq[B_ * Q_ * T_];

// ---------------- reduction helpers ----------------
DEV_INLINE float blockReduceSum1(float v, float* red, int tid) {
    #pragma unroll
    for (int o = 16; o; o >>= 1) v += __shfl_xor_sync(0xffffffffu, v, o);
    int warp = tid >> 5, lane = tid & 31;
    int nw = blockDim.x >> 5;
    __syncthreads();
    if (lane == 0) red[warp] = v;
    __syncthreads();
    if (tid == 0) {
        float s = 0.f;
        for (int w = 0; w < nw; w++) s += red[w];
        red[0] = s;
    }
    __syncthreads();
    float r = red[0];
    __syncthreads();
    return r;
}

template <int NV>
DEV_INLINE void blockReduceSumArr(float* v, float* red, int tid) {
    #pragma unroll
    for (int i = 0; i < NV; i++)
        #pragma unroll
        for (int o = 16; o; o >>= 1) v[i] += __shfl_xor_sync(0xffffffffu, v[i], o);
    int warp = tid >> 5, lane = tid & 31;
    int nw = blockDim.x >> 5;
    __syncthreads();
    if (lane == 0)
        #pragma unroll
        for (int i = 0; i < NV; i++) red[warp * NV + i] = v[i];
    __syncthreads();
    if (tid == 0) {
        for (int w = 1; w < nw; w++)
            #pragma unroll
            for (int i = 0; i < NV; i++) red[i] += red[w * NV + i];
    }
    __syncthreads();
    #pragma unroll
    for (int i = 0; i < NV; i++) v[i] = red[i];
    __syncthreads();
}

template <int NV>
DEV_INLINE void blockReduceMaxArr(float* v, float* red, int tid) {
    #pragma unroll
    for (int i = 0; i < NV; i++)
        #pragma unroll
        for (int o = 16; o; o >>= 1) v[i] = fmaxf(v[i], __shfl_xor_sync(0xffffffffu, v[i], o));
    int warp = tid >> 5, lane = tid & 31;
    int nw = blockDim.x >> 5;
    __syncthreads();
    if (lane == 0)
        #pragma unroll
        for (int i = 0; i < NV; i++) red[warp * NV + i] = v[i];
    __syncthreads();
    if (tid == 0) {
        for (int w = 1; w < nw; w++)
            #pragma unroll
            for (int i = 0; i < NV; i++) red[i] = fmaxf(red[i], red[w * NV + i]);
    }
    __syncthreads();
    #pragma unroll
    for (int i = 0; i < NV; i++) v[i] = red[i];
    __syncthreads();
}

DEV_INLINE float sigmoidf(float x) { return 1.f / (1.f + expf(-x)); }

// ---------------- K1: feat_shot partial sums ----------------
__global__ void k1_partial(const float* __restrict__ feat_shot) {
    int bn = blockIdx.y, chunk = blockIdx.x, c = threadIdx.x;
    const float* p = feat_shot + ((size_t)bn * T_ + chunk * 14) * C_ + c;
    float s0 = 0.f, s1 = 0.f;
    #pragma unroll
    for (int t = 0; t < 14; t += 2) {
        s0 += p[(size_t)t * C_];
        s1 += p[(size_t)(t + 1) * C_];
    }
    g_part[(bn * TCH_ + chunk) * C_ + c] = s0 + s1;
}

// ---------------- K2 layer 1 (fused: computes means from g_part inline) ----------------
__global__ void __launch_bounds__(256) k2_mlp1(const float* __restrict__ w1t, const float* __restrict__ b1t,
                                               const float* __restrict__ w1c, const float* __restrict__ b1c) {
    __shared__ float xs[12 * C_];
    __shared__ float part[8 * 12 * 32];
    int tid = threadIdx.x;
    // cls mean rows 2..11 from partials (independent 14-load sums, fully batched)
    for (int i = tid; i < 10 * C_; i += 256) {
        int bn = i / C_, c = i % C_;
        const float* p = g_part + (size_t)bn * TCH_ * C_ + c;
        float a0 = 0.f, a1 = 0.f;
        #pragma unroll
        for (int k = 0; k < TCH_; k += 2) {
            a0 += p[(size_t)k * C_];
            a1 += p[(size_t)(k + 1) * C_];
        }
        xs[(2 + bn) * C_ + c] = (a0 + a1) * (1.f / T_);
    }
    __syncthreads();
    // task rows 0..1 = mean over n of cls rows (matches old (sum/T)/N order)
    for (int i = tid; i < 2 * C_; i += 256) {
        int r = i / C_, c = i % C_;
        float s = 0.f;
        #pragma unroll
        for (int n = 0; n < N_; n++) s += xs[(2 + r * N_ + n) * C_ + c];
        xs[r * C_ + c] = s * (1.f / N_);
    }
    __syncthreads();
    int w = tid >> 5, l = tid & 31;
    int j = blockIdx.x * 32 + l;
    float acc[12];
    #pragma unroll
    for (int r = 0; r < 12; r++) acc[r] = 0.f;
    int c0 = w * 48;
    float nwt = w1t[(size_t)c0 * H_ + j];
    float nwc = w1c[(size_t)c0 * H_ + j];
    for (int c = c0; c < c0 + 48; c++) {
        float wt = nwt, wc = nwc;
        if (c + 1 < c0 + 48) {
            nwt = w1t[(size_t)(c + 1) * H_ + j];
            nwc = w1c[(size_t)(c + 1) * H_ + j];
        }
        acc[0] += xs[0 * C_ + c] * wt;
        acc[1] += xs[1 * C_ + c] * wt;
        #pragma unroll
        for (int r = 2; r < 12; r++) acc[r] += xs[r * C_ + c] * wc;
    }
    #pragma unroll
    for (int r = 0; r < 12; r++) part[(w * 12 + r) * 32 + l] = acc[r];
    __syncthreads();
    for (int idx = tid; idx < 12 * 32; idx += 256) {
        int r = idx / 32, ll = idx % 32;
        float s = 0.f;
        #pragma unroll
        for (int ww = 0; ww < 8; ww++) s += part[(ww * 12 + r) * 32 + ll];
        int jj = blockIdx.x * 32 + ll;
        float bias = (r < B_) ? b1t[jj] : b1c[jj];
        g_hidden[r * H_ + jj] = fmaxf(s + bias, 0.f);
    }
}

// ---------------- K2 layer 2, stage A (unchanged) ----------------
__global__ void __launch_bounds__(512) k2_mlp2A(const float* __restrict__ w2t,
                                                const float* __restrict__ w2c) {
    __shared__ float hid_s[192];
    __shared__ float4 part4[16][32];
    int ct = blockIdx.x, row = blockIdx.y, z = blockIdx.z;
    int tid = threadIdx.x;
    if (tid < 192) hid_s[tid] = g_hidden[row * H_ + z * 192 + tid];
    __syncthreads();
    int jg = tid >> 5, q = tid & 31;
    int cbase = ct * 128 + q * 4;
    const float* w2 = (row < B_) ? w2t : w2c;
    int jl0 = jg * 12;
    const float* wp = w2 + (size_t)(z * 192 + jl0) * C_ + cbase;

    float4 a = make_float4(0.f, 0.f, 0.f, 0.f);
    float4 nf = *(const float4*)wp;
    #pragma unroll
    for (int jj = 0; jj < 12; jj++) {
        float4 f = nf;
        if (jj + 1 < 12) nf = *(const float4*)(wp + (size_t)(jj + 1) * C_);
        float m = hid_s[jl0 + jj];
        a.x += f.x * m; a.y += f.y * m; a.z += f.z * m; a.w += f.w * m;
    }
    part4[jg][q] = a;
    __syncthreads();
    if (tid < 32) {
        float4 s = part4[0][tid];
        #pragma unroll
        for (int g = 1; g < 16; g++) {
            float4 t = part4[g][tid];
            s.x += t.x; s.y += t.y; s.z += t.z; s.w += t.w;
        }
        *(float4*)&g_p2[(size_t)(z * 12 + row) * C_ + ct * 128 + tid * 4] = s;
    }
}

// ---------------- K2c: shot-side (fused: computes wc/wt/u from g_p2 inline) ----------------
__global__ void __launch_bounds__(768) k2c_shot(const float* __restrict__ feat_shot,
                                                const float* __restrict__ x_shot,
                                                const float* __restrict__ b2t,
                                                const float* __restrict__ b2c) {
    __shared__ float wc_s[C_];
    __shared__ float wt_s[C_];
    __shared__ float u_s[C_];
    __shared__ float map_s[T_];
    __shared__ float red[32];
    __shared__ float4 part4[8][96];
    int bn = blockIdx.x, b = bn / N_, tid = threadIdx.x;
    int warp = tid >> 5, lane = tid & 31;

    // fold of mlp2B: wc row (2+bn) + wt row b from g_p2 (stride 12*C per z-chunk)
    if (tid < C_) {
        int c = tid;
        const float* p = g_p2 + (size_t)(2 + bn) * C_ + c;
        float s0 = 0.f, s1 = 0.f, s2 = 0.f, s3 = 0.f;
        #pragma unroll
        for (int z = 0; z < JCH_; z += 4) {
            s0 += p[(size_t)(z + 0) * 12 * C_];
            s1 += p[(size_t)(z + 1) * 12 * C_];
            s2 += p[(size_t)(z + 2) * 12 * C_];
            s3 += p[(size_t)(z + 3) * 12 * C_];
        }
        float wc = sigmoidf((s0 + s1) + (s2 + s3) + b2c[c]);
        wc_s[c] = wc;
        g_wc[bn * C_ + c] = wc;
    } else {
        int c = tid - C_;
        const float* p = g_p2 + (size_t)b * C_ + c;
        float s0 = 0.f, s1 = 0.f, s2 = 0.f, s3 = 0.f;
        #pragma unroll
        for (int z = 0; z < JCH_; z += 4) {
            s0 += p[(size_t)(z + 0) * 12 * C_];
            s1 += p[(size_t)(z + 1) * 12 * C_];
            s2 += p[(size_t)(z + 2) * 12 * C_];
            s3 += p[(size_t)(z + 3) * 12 * C_];
        }
        wt_s[c] = (s0 + s1) + (s2 + s3) + b2t[c];
    }
    __syncthreads();
    if (tid < C_) {
        float uval = wc_s[tid] * wt_s[tid];
        g_u[bn * C_ + tid] = uval;
        u_s[tid] = uval;
    }
    __syncthreads();

    const float* fsr = feat_shot + (size_t)bn * T_ * C_;
    for (int t = warp; t < T_; t += 24) {
        float ss = 0.f, du = 0.f;
        for (int c = lane; c < C_; c += 32) {
            float f = fsr[t * C_ + c];
            ss += f * f;
            du += f * u_s[c];
        }
        #pragma unroll
        for (int o = 16; o; o >>= 1) {
            ss += __shfl_xor_sync(0xffffffffu, ss, o);
            du += __shfl_xor_sync(0xffffffffu, du, o);
        }
        if (lane == 0) {
            g_ns[bn * T_ + t] = sqrtf(ss);
            map_s[t] = sigmoidf(du);
        }
    }
    __syncthreads();
    int tg = tid / 96, q = tid % 96;
    int start = (tg < 4) ? tg * 25 : 100 + (tg - 4) * 24;
    int len = (tg < 4) ? 25 : 24;
    int cbase = q * 4;
    const float* p = fsr + (size_t)start * C_ + cbase;
    float4 a = make_float4(0.f, 0.f, 0.f, 0.f);
    float4 nf = *(const float4*)p;
    for (int i = 0; i < len; i++) {
        float4 f = nf;
        if (i + 1 < len) nf = *(const float4*)(p + (size_t)(i + 1) * C_);
        float m = map_s[start + i];
        a.x += f.x * m; a.y += f.y * m; a.z += f.z * m; a.w += f.w * m;
    }
    part4[tg][q] = a;
    __syncthreads();
    float4 v4 = make_float4(0.f, 0.f, 0.f, 0.f);
    float loc = 0.f;
    if (tid < 96) {
        float4 s = part4[0][tid];
        #pragma unroll
        for (int g = 1; g < 8; g++) {
            float4 t = part4[g][tid];
            s.x += t.x; s.y += t.y; s.z += t.z; s.w += t.w;
        }
        float4 wc4 = *(const float4*)&wc_s[tid * 4];
        v4.x = wc4.x * s.x * (1.f / T_);
        v4.y = wc4.y * s.y * (1.f / T_);
        v4.z = wc4.z * s.z * (1.f / T_);
        v4.w = wc4.w * s.w * (1.f / T_);
        loc = v4.x * v4.x + v4.y * v4.y + v4.z * v4.z + v4.w * v4.w;
    }
    float s2 = blockReduceSum1(loc, red, tid);
    if (tid < 96) {
        float inv = 1.f / (1e-16f + sqrtf(s2));
        float4 o = make_float4(v4.x * inv, v4.y * inv, v4.z * inv, v4.w * inv);
        *(float4*)&g_xsrw[bn * C_ + tid * 4] = o;
    }
    float4 xq4 = make_float4(0.f, 0.f, 0.f, 0.f);
    float loc2 = 0.f;
    if (tid < 96) {
        xq4 = *(const float4*)&x_shot[(size_t)bn * C_ + tid * 4];
        loc2 = xq4.x * xq4.x + xq4.y * xq4.y + xq4.z * xq4.z + xq4.w * xq4.w;
    }
    float n2 = blockReduceSum1(loc2, red, tid);
    if (tid < 96) {
        float inv = 1.f / fmaxf(sqrtf(n2), 1e-12f);
        float4 o = make_float4(xq4.x * inv, xq4.y * inv, xq4.z * inv, xq4.w * inv);
        *(float4*)&g_xshat[bn * C_ + tid * 4] = o;
    }
}

// ---------------- K3: pass 1 (unchanged) ----------------
__global__ void __launch_bounds__(256) k3_pass1(const float* __restrict__ feat_query,
                                                const float* __restrict__ feat_shot) {
    __shared__ float fs_s[2 * N_ * C_];
    __shared__ float u_s[N_ * C_];
    int b = blockIdx.y, t0 = blockIdx.x * 2, tid = threadIdx.x;
    for (int i = tid; i < 2 * N_ * C_; i += 256) {
        int tt = i / (N_ * C_), r = i % (N_ * C_);
        int n = r / C_, c = r % C_;
        fs_s[i] = feat_shot[((size_t)(b * N_ + n) * T_ + t0 + tt) * C_ + c];
    }
    for (int i = tid; i < N_ * C_; i += 256) u_s[i] = g_u[b * N_ * C_ + i];
    __syncthreads();

    int warp = tid >> 5, lane = tid & 31;
    for (int task = warp; task < 38; task += 8) {
        int tt = task / 19, qi = task % 19;
        int t = t0 + tt, q0 = qi * 4;

        float4 fq[4][3];
        #pragma unroll
        for (int qq = 0; qq < 4; qq++) {
            int q = q0 + qq;
            if (q < Q_) {
                const float* p = feat_query + (((size_t)(b * Q_ + q)) * T_ + t) * C_;
                #pragma unroll
                for (int j = 0; j < 3; j++)
                    fq[qq][j] = *(const float4*)(p + 4 * (lane + 32 * j));
            } else {
                #pragma unroll
                for (int j = 0; j < 3; j++) fq[qq][j] = make_float4(0.f, 0.f, 0.f, 0.f);
            }
        }

        float acc[44];
        #pragma unroll
        for (int i = 0; i < 44; i++) acc[i] = 0.f;

        #pragma unroll
        for (int j = 0; j < 3; j++) {
            int cb = 4 * (lane + 32 * j);
            #pragma unroll
            for (int n = 0; n < N_; n++) {
                float4 s4 = *(const float4*)&fs_s[(tt * N_ + n) * C_ + cb];
                float4 u4 = *(const float4*)&u_s[n * C_ + cb];
                #pragma unroll
                for (int qq = 0; qq < 4; qq++) {
                    float4 f = fq[qq][j];
                    acc[qq * 5 + n]      += f.x * s4.x + f.y * s4.y + f.z * s4.z + f.w * s4.w;
                    acc[20 + qq * 5 + n] += f.x * u4.x + f.y * u4.y + f.z * u4.z + f.w * u4.w;
                }
            }
            #pragma unroll
            for (int qq = 0; qq < 4; qq++) {
                float4 f = fq[qq][j];
                acc[40 + qq] += f.x * f.x + f.y * f.y + f.z * f.z + f.w * f.w;
            }
        }

        #pragma unroll
        for (int i = 0; i < 44; i++)
            #pragma unroll
            for (int o = 16; o; o >>= 1) acc[i] += __shfl_xor_sync(0xffffffffu, acc[i], o);

        if (lane == 0) {
            #pragma unroll
            for (int qq = 0; qq < 4; qq++) {
                int q = q0 + qq;
                if (q < Q_) {
                    size_t base = (size_t)(b * Q_ + q) * N_ * T_;
                    #pragma unroll
                    for (int n = 0; n < N_; n++) {
                        g_num[base + n * T_ + t] = acc[qq * 5 + n];
                        g_dq[base + n * T_ + t]  = acc[20 + qq * 5 + n];
                    }
                    g_nq[(b * Q_ + q) * T_ + t] = sqrtf(acc[40 + qq]);
                }
            }
        }
    }
}

// ---------------- K4: pass 2 (unchanged) ----------------
__global__ void __launch_bounds__(384) k4_pass2(const float* __restrict__ feat_query,
                                                const float* __restrict__ x_query,
                                                float* __restrict__ out) {
    __shared__ float map_s[N_ * T_];
    __shared__ float4 part4[4 * N_ * 96];
    __shared__ float accf[N_ * C_];
    __shared__ float red[128];

    int q = blockIdx.x, b = blockIdx.y, tid = threadIdx.x;
    int bq = b * Q_ + q;
    size_t nt_base = (size_t)bq * N_ * T_;

    float mx[N_];
    #pragma unroll
    for (int n = 0; n < N_; n++) mx[n] = -1e30f;
    if (tid < T_) {
        float nqv = g_nq[bq * T_ + tid];
        #pragma unroll
        for (int n = 0; n < N_; n++) {
            float denom = fmaxf(nqv * g_ns[(b * N_ + n) * T_ + tid], 1e-8f);
            mx[n] = g_num[nt_base + n * T_ + tid] / denom;
        }
    }
    blockReduceMaxArr<N_>(mx, red, tid);
    if (tid == 0) {
        float lg = (mx[0] + mx[1] + mx[2] + mx[3] + mx[4]) * (1.f / N_);
        out[bq] = lg;
        out[B_ * Q_ + bq] = lg;
    }

    for (int i = tid; i < N_ * T_; i += 384) map_s[i] = sigmoidf(g_dq[nt_base + i]);
    __syncthreads();

    int g = tid / 96, cg = tid % 96;
    float4 acc[N_];
    #pragma unroll
    for (int n = 0; n < N_; n++) acc[n] = make_float4(0.f, 0.f, 0.f, 0.f);
    const float* fqp = feat_query + ((size_t)bq * T_ + g * 49) * C_ + 4 * cg;
    float4 nf = *(const float4*)fqp;
    for (int t = 0; t < 49; t++) {
        float4 f = nf;
        if (t + 1 < 49) nf = *(const float4*)(fqp + (size_t)(t + 1) * C_);
        int tg = g * 49 + t;
        #pragma unroll
        for (int n = 0; n < N_; n++) {
            float m = map_s[n * T_ + tg];
            acc[n].x += f.x * m; acc[n].y += f.y * m;
            acc[n].z += f.z * m; acc[n].w += f.w * m;
        }
    }
    #pragma unroll
    for (int n = 0; n < N_; n++) part4[(g * N_ + n) * 96 + cg] = acc[n];
    __syncthreads();
    for (int idx = tid; idx < N_ * 96; idx += 384) {
        int n = idx / 96, c4 = idx % 96;
        float4 s0 = part4[(0 * N_ + n) * 96 + c4];
        float4 s1 = part4[(1 * N_ + n) * 96 + c4];
        float4 s2 = part4[(2 * N_ + n) * 96 + c4];
        float4 s3 = part4[(3 * N_ + n) * 96 + c4];
        float4 s;
        s.x = s0.x + s1.x + s2.x + s3.x;
        s.y = s0.y + s1.y + s2.y + s3.y;
        s.z = s0.z + s1.z + s2.z + s3.z;
        s.w = s0.w + s1.w + s2.w + s3.w;
        *(float4*)&accf[n * C_ + 4 * c4] = s;
    }
    __syncthreads();

    int c = tid;
    #pragma unroll
    for (int n = 0; n < N_; n++) {
        float v = g_wc[(b * N_ + n) * C_ + c] * accf[n * C_ + c] * (1.f / T_);
        float pr[2] = { v * v, v * g_xsrw[(b * N_ + n) * C_ + c] };
        blockReduceSumArr<2>(pr, red, tid);
        if (tid == 0)
            out[2 * B_ * Q_ + B_ * Q_ * N_ + bq * N_ + n] = pr[1] / (1e-16f + sqrtf(pr[0]));
    }

    float xv = x_query[(size_t)bq * C_ + c];
    float pr6[6];
    pr6[0] = xv * xv;
    #pragma unroll
    for (int n = 0; n < N_; n++) pr6[1 + n] = xv * g_xshat[(b * N_ + n) * C_ + c];
    blockReduceSumArr<6>(pr6, red, tid);
    if (tid == 0) {
        float qn = fmaxf(sqrtf(pr6[0]), 1e-12f);
        #pragma unroll
        for (int n = 0; n < N_; n++)
            out[2 * B_ * Q_ + bq * N_ + n] = TEMP_ * pr6[1 + n] / qn;
    }
}

// ---------------- launch (6 nodes) ----------------
extern "C" void kernel_launch(void* const* d_in, const int* in_sizes, int n_in,
                              void* d_out, int out_size) {
    const float* feat_shot  = (const float*)d_in[0];
    const float* feat_query = (const float*)d_in[1];
    const float* x_shot     = (const float*)d_in[2];
    const float* x_query    = (const float*)d_in[3];
    const float* w1_task    = (const float*)d_in[4];
    const float* b1_task    = (const float*)d_in[5];
    const float* w2_task    = (const float*)d_in[6];
    const float* b2_task    = (const float*)d_in[7];
    const float* w1_cls     = (const float*)d_in[8];
    const float* b1_cls     = (const float*)d_in[9];
    const float* w2_cls     = (const float*)d_in[10];
    const float* b2_cls     = (const float*)d_in[11];
    float* out = (float*)d_out;

    k1_partial<<<dim3(TCH_, B_ * N_), C_>>>(feat_shot);
    k2_mlp1<<<H_ / 32, 256>>>(w1_task, b1_task, w1_cls, b1_cls);
    k2_mlp2A<<<dim3(3, 12, JCH_), 512>>>(w2_task, w2_cls);
    k2c_shot<<<B_ * N_, 768>>>(feat_shot, x_shot, b2_task, b2_cls);
    k3_pass1<<<dim3(98, B_), 256>>>(feat_query, feat_shot);
    k4_pass2<<<dim3(Q_, B_), 384>>>(feat_query, x_query, out);
}

// round 14
// speedup vs baseline: 1.5176x; 1.0537x over previous
#include <cuda_runtime.h>
#include <math.h>

#define DEV_INLINE __device__ __forceinline__

constexpr int B_ = 2, Q_ = 75, N_ = 5, T_ = 196, C_ = 384, H_ = 1536;
constexpr float TEMP_ = 10.0f;
constexpr int TCH_ = 14;                  // t-chunks for k1 (14*14=196)
constexpr int JCH_ = 8;                   // j-chunks for mlp2 (8*192=1536)
constexpr int SCH_ = 8;                   // t-chunks for k2c (4x25 + 4x24)

// ---------------- scratch (device globals; no allocation) ----------------
__device__ float g_part[B_ * N_ * TCH_ * C_];
__device__ float g_hidden[(B_ + B_ * N_) * H_]; // rows 0..1 task, 2..11 cls
__device__ float g_p2[JCH_ * 12 * C_];          // mlp2 partials [jchunk][row][c]
__device__ float g_wc[B_ * N_ * C_];
__device__ float g_u[B_ * N_ * C_];
__device__ float g_ns[B_ * N_ * T_];
__device__ float g_accp[B_ * N_ * SCH_ * C_];   // shot-side t-partials
__device__ float g_num[B_ * Q_ * N_ * T_];
__device__ float g_dq[B_ * Q_ * N_ * T_];
__device__ float g_nq[B_ * Q_ * T_];

// ---------------- reduction helpers ----------------
DEV_INLINE float blockReduceSum1(float v, float* red, int tid) {
    #pragma unroll
    for (int o = 16; o; o >>= 1) v += __shfl_xor_sync(0xffffffffu, v, o);
    int warp = tid >> 5, lane = tid & 31;
    int nw = blockDim.x >> 5;
    __syncthreads();
    if (lane == 0) red[warp] = v;
    __syncthreads();
    if (tid == 0) {
        float s = 0.f;
        for (int w = 0; w < nw; w++) s += red[w];
        red[0] = s;
    }
    __syncthreads();
    float r = red[0];
    __syncthreads();
    return r;
}

template <int NV>
DEV_INLINE void blockReduceSumArr(float* v, float* red, int tid) {
    #pragma unroll
    for (int i = 0; i < NV; i++)
        #pragma unroll
        for (int o = 16; o; o >>= 1) v[i] += __shfl_xor_sync(0xffffffffu, v[i], o);
    int warp = tid >> 5, lane = tid & 31;
    int nw = blockDim.x >> 5;
    __syncthreads();
    if (lane == 0)
        #pragma unroll
        for (int i = 0; i < NV; i++) red[warp * NV + i] = v[i];
    __syncthreads();
    if (tid == 0) {
        for (int w = 1; w < nw; w++)
            #pragma unroll
            for (int i = 0; i < NV; i++) red[i] += red[w * NV + i];
    }
    __syncthreads();
    #pragma unroll
    for (int i = 0; i < NV; i++) v[i] = red[i];
    __syncthreads();
}

template <int NV>
DEV_INLINE void blockReduceMaxArr(float* v, float* red, int tid) {
    #pragma unroll
    for (int i = 0; i < NV; i++)
        #pragma unroll
        for (int o = 16; o; o >>= 1) v[i] = fmaxf(v[i], __shfl_xor_sync(0xffffffffu, v[i], o));
    int warp = tid >> 5, lane = tid & 31;
    int nw = blockDim.x >> 5;
    __syncthreads();
    if (lane == 0)
        #pragma unroll
        for (int i = 0; i < NV; i++) red[warp * NV + i] = v[i];
    __syncthreads();
    if (tid == 0) {
        for (int w = 1; w < nw; w++)
            #pragma unroll
            for (int i = 0; i < NV; i++) red[i] = fmaxf(red[i], red[w * NV + i]);
    }
    __syncthreads();
    #pragma unroll
    for (int i = 0; i < NV; i++) v[i] = red[i];
    __syncthreads();
}

DEV_INLINE float sigmoidf(float x) { return 1.f / (1.f + expf(-x)); }

// ---------------- K1: feat_shot partial sums ----------------
__global__ void k1_partial(const float* __restrict__ feat_shot) {
    int bn = blockIdx.y, chunk = blockIdx.x, c = threadIdx.x;
    const float* p = feat_shot + ((size_t)bn * T_ + chunk * 14) * C_ + c;
    float s0 = 0.f, s1 = 0.f;
    #pragma unroll
    for (int t = 0; t < 14; t += 2) {
        s0 += p[(size_t)t * C_];
        s1 += p[(size_t)(t + 1) * C_];
    }
    g_part[(bn * TCH_ + chunk) * C_ + c] = s0 + s1;
}

// ---------------- K2 layer 1 (computes means from g_part inline) ----------------
__global__ void __launch_bounds__(256) k2_mlp1(const float* __restrict__ w1t, const float* __restrict__ b1t,
                                               const float* __restrict__ w1c, const float* __restrict__ b1c) {
    __shared__ float xs[12 * C_];
    __shared__ float part[8 * 12 * 32];
    int tid = threadIdx.x;
    for (int i = tid; i < 10 * C_; i += 256) {
        int bn = i / C_, c = i % C_;
        const float* p = g_part + (size_t)bn * TCH_ * C_ + c;
        float a0 = 0.f, a1 = 0.f;
        #pragma unroll
        for (int k = 0; k < TCH_; k += 2) {
            a0 += p[(size_t)k * C_];
            a1 += p[(size_t)(k + 1) * C_];
        }
        xs[(2 + bn) * C_ + c] = (a0 + a1) * (1.f / T_);
    }
    __syncthreads();
    for (int i = tid; i < 2 * C_; i += 256) {
        int r = i / C_, c = i % C_;
        float s = 0.f;
        #pragma unroll
        for (int n = 0; n < N_; n++) s += xs[(2 + r * N_ + n) * C_ + c];
        xs[r * C_ + c] = s * (1.f / N_);
    }
    __syncthreads();
    int w = tid >> 5, l = tid & 31;
    int j = blockIdx.x * 32 + l;
    float acc[12];
    #pragma unroll
    for (int r = 0; r < 12; r++) acc[r] = 0.f;
    int c0 = w * 48;
    float nwt = w1t[(size_t)c0 * H_ + j];
    float nwc = w1c[(size_t)c0 * H_ + j];
    for (int c = c0; c < c0 + 48; c++) {
        float wt = nwt, wc = nwc;
        if (c + 1 < c0 + 48) {
            nwt = w1t[(size_t)(c + 1) * H_ + j];
            nwc = w1c[(size_t)(c + 1) * H_ + j];
        }
        acc[0] += xs[0 * C_ + c] * wt;
        acc[1] += xs[1 * C_ + c] * wt;
        #pragma unroll
        for (int r = 2; r < 12; r++) acc[r] += xs[r * C_ + c] * wc;
    }
    #pragma unroll
    for (int r = 0; r < 12; r++) part[(w * 12 + r) * 32 + l] = acc[r];
    __syncthreads();
    for (int idx = tid; idx < 12 * 32; idx += 256) {
        int r = idx / 32, ll = idx % 32;
        float s = 0.f;
        #pragma unroll
        for (int ww = 0; ww < 8; ww++) s += part[(ww * 12 + r) * 32 + ll];
        int jj = blockIdx.x * 32 + ll;
        float bias = (r < B_) ? b1t[jj] : b1c[jj];
        g_hidden[r * H_ + jj] = fmaxf(s + bias, 0.f);
    }
}

// ---------------- K2 layer 2, stage A (unchanged) ----------------
__global__ void __launch_bounds__(512) k2_mlp2A(const float* __restrict__ w2t,
                                                const float* __restrict__ w2c) {
    __shared__ float hid_s[192];
    __shared__ float4 part4[16][32];
    int ct = blockIdx.x, row = blockIdx.y, z = blockIdx.z;
    int tid = threadIdx.x;
    if (tid < 192) hid_s[tid] = g_hidden[row * H_ + z * 192 + tid];
    __syncthreads();
    int jg = tid >> 5, q = tid & 31;
    int cbase = ct * 128 + q * 4;
    const float* w2 = (row < B_) ? w2t : w2c;
    int jl0 = jg * 12;
    const float* wp = w2 + (size_t)(z * 192 + jl0) * C_ + cbase;

    float4 a = make_float4(0.f, 0.f, 0.f, 0.f);
    float4 nf = *(const float4*)wp;
    #pragma unroll
    for (int jj = 0; jj < 12; jj++) {
        float4 f = nf;
        if (jj + 1 < 12) nf = *(const float4*)(wp + (size_t)(jj + 1) * C_);
        float m = hid_s[jl0 + jj];
        a.x += f.x * m; a.y += f.y * m; a.z += f.z * m; a.w += f.w * m;
    }
    part4[jg][q] = a;
    __syncthreads();
    if (tid < 32) {
        float4 s = part4[0][tid];
        #pragma unroll
        for (int g = 1; g < 16; g++) {
            float4 t = part4[g][tid];
            s.x += t.x; s.y += t.y; s.z += t.z; s.w += t.w;
        }
        *(float4*)&g_p2[(size_t)(z * 12 + row) * C_ + ct * 128 + tid * 4] = s;
    }
}

// ---------------- K2c: shot-side, grid (8 t-chunks, B*N) = 80 blocks, 384 thr ----------------
__global__ void __launch_bounds__(384) k2c_shot(const float* __restrict__ feat_shot,
                                                const float* __restrict__ b2t,
                                                const float* __restrict__ b2c) {
    __shared__ float u_s[C_];
    __shared__ float fs_s[25 * C_];   // 38.4 KB
    __shared__ float map_s[25];
    int tg = blockIdx.x, bn = blockIdx.y, b = bn / N_;
    int tid = threadIdx.x;
    int warp = tid >> 5, lane = tid & 31;
    int start = (tg < 4) ? tg * 25 : 100 + (tg - 4) * 24;
    int len = (tg < 4) ? 25 : 24;
    int c = tid;  // 384 threads == C

    // mlp2B fold: wc row (2+bn), wt row b from g_p2 (same summation order as before)
    {
        const float* pc = g_p2 + (size_t)(2 + bn) * C_ + c;
        const float* pt = g_p2 + (size_t)b * C_ + c;
        float s0 = 0.f, s1 = 0.f, s2 = 0.f, s3 = 0.f;
        float r0 = 0.f, r1 = 0.f, r2 = 0.f, r3 = 0.f;
        #pragma unroll
        for (int z = 0; z < JCH_; z += 4) {
            s0 += pc[(size_t)(z + 0) * 12 * C_];
            s1 += pc[(size_t)(z + 1) * 12 * C_];
            s2 += pc[(size_t)(z + 2) * 12 * C_];
            s3 += pc[(size_t)(z + 3) * 12 * C_];
            r0 += pt[(size_t)(z + 0) * 12 * C_];
            r1 += pt[(size_t)(z + 1) * 12 * C_];
            r2 += pt[(size_t)(z + 2) * 12 * C_];
            r3 += pt[(size_t)(z + 3) * 12 * C_];
        }
        float wc = sigmoidf((s0 + s1) + (s2 + s3) + b2c[c]);
        float wt = (r0 + r1) + (r2 + r3) + b2t[c];
        float uv = wc * wt;
        u_s[c] = uv;
        if (tg == 0) {
            g_wc[bn * C_ + c] = wc;
            g_u[bn * C_ + c] = uv;
        }
    }

    // stage fs chunk in SMEM (4-batched loads)
    const float* fsr = feat_shot + ((size_t)bn * T_ + start) * C_;
    {
        int i = 0;
        for (; i + 4 <= len; i += 4) {
            float f0 = fsr[(size_t)(i + 0) * C_ + tid];
            float f1 = fsr[(size_t)(i + 1) * C_ + tid];
            float f2 = fsr[(size_t)(i + 2) * C_ + tid];
            float f3 = fsr[(size_t)(i + 3) * C_ + tid];
            fs_s[(i + 0) * C_ + tid] = f0;
            fs_s[(i + 1) * C_ + tid] = f1;
            fs_s[(i + 2) * C_ + tid] = f2;
            fs_s[(i + 3) * C_ + tid] = f3;
        }
        for (; i < len; i++) fs_s[i * C_ + tid] = fsr[(size_t)i * C_ + tid];
    }
    __syncthreads();

    // per-t norms + map logits from SMEM (12 warps stride t)
    for (int i = warp; i < len; i += 12) {
        float ss = 0.f, du = 0.f;
        for (int cc = lane; cc < C_; cc += 32) {
            float f = fs_s[i * C_ + cc];
            ss += f * f;
            du += f * u_s[cc];
        }
        #pragma unroll
        for (int o = 16; o; o >>= 1) {
            ss += __shfl_xor_sync(0xffffffffu, ss, o);
            du += __shfl_xor_sync(0xffffffffu, du, o);
        }
        if (lane == 0) {
            g_ns[bn * T_ + start + i] = sqrtf(ss);
            map_s[i] = sigmoidf(du);
        }
    }
    __syncthreads();

    // t-partial acc (SMEM reads, conflict-free)
    float a = 0.f;
    for (int i = 0; i < len; i++) a += fs_s[i * C_ + c] * map_s[i];
    g_accp[(size_t)(bn * SCH_ + tg) * C_ + c] = a;
}

// ---------------- K3: pass 1 (unchanged) ----------------
__global__ void __launch_bounds__(256) k3_pass1(const float* __restrict__ feat_query,
                                                const float* __restrict__ feat_shot) {
    __shared__ float fs_s[2 * N_ * C_];
    __shared__ float u_s[N_ * C_];
    int b = blockIdx.y, t0 = blockIdx.x * 2, tid = threadIdx.x;
    for (int i = tid; i < 2 * N_ * C_; i += 256) {
        int tt = i / (N_ * C_), r = i % (N_ * C_);
        int n = r / C_, c = r % C_;
        fs_s[i] = feat_shot[((size_t)(b * N_ + n) * T_ + t0 + tt) * C_ + c];
    }
    for (int i = tid; i < N_ * C_; i += 256) u_s[i] = g_u[b * N_ * C_ + i];
    __syncthreads();

    int warp = tid >> 5, lane = tid & 31;
    for (int task = warp; task < 38; task += 8) {
        int tt = task / 19, qi = task % 19;
        int t = t0 + tt, q0 = qi * 4;

        float4 fq[4][3];
        #pragma unroll
        for (int qq = 0; qq < 4; qq++) {
            int q = q0 + qq;
            if (q < Q_) {
                const float* p = feat_query + (((size_t)(b * Q_ + q)) * T_ + t) * C_;
                #pragma unroll
                for (int j = 0; j < 3; j++)
                    fq[qq][j] = *(const float4*)(p + 4 * (lane + 32 * j));
            } else {
                #pragma unroll
                for (int j = 0; j < 3; j++) fq[qq][j] = make_float4(0.f, 0.f, 0.f, 0.f);
            }
        }

        float acc[44];
        #pragma unroll
        for (int i = 0; i < 44; i++) acc[i] = 0.f;

        #pragma unroll
        for (int j = 0; j < 3; j++) {
            int cb = 4 * (lane + 32 * j);
            #pragma unroll
            for (int n = 0; n < N_; n++) {
                float4 s4 = *(const float4*)&fs_s[(tt * N_ + n) * C_ + cb];
                float4 u4 = *(const float4*)&u_s[n * C_ + cb];
                #pragma unroll
                for (int qq = 0; qq < 4; qq++) {
                    float4 f = fq[qq][j];
                    acc[qq * 5 + n]      += f.x * s4.x + f.y * s4.y + f.z * s4.z + f.w * s4.w;
                    acc[20 + qq * 5 + n] += f.x * u4.x + f.y * u4.y + f.z * u4.z + f.w * u4.w;
                }
            }
            #pragma unroll
            for (int qq = 0; qq < 4; qq++) {
                float4 f = fq[qq][j];
                acc[40 + qq] += f.x * f.x + f.y * f.y + f.z * f.z + f.w * f.w;
            }
        }

        #pragma unroll
        for (int i = 0; i < 44; i++)
            #pragma unroll
            for (int o = 16; o; o >>= 1) acc[i] += __shfl_xor_sync(0xffffffffu, acc[i], o);

        if (lane == 0) {
            #pragma unroll
            for (int qq = 0; qq < 4; qq++) {
                int q = q0 + qq;
                if (q < Q_) {
                    size_t base = (size_t)(b * Q_ + q) * N_ * T_;
                    #pragma unroll
                    for (int n = 0; n < N_; n++) {
                        g_num[base + n * T_ + t] = acc[qq * 5 + n];
                        g_dq[base + n * T_ + t]  = acc[20 + qq * 5 + n];
                    }
                    g_nq[(b * Q_ + q) * T_ + t] = sqrtf(acc[40 + qq]);
                }
            }
        }
    }
}

// ---------------- K4: pass 2 (combines shot partials + both normalizations) ----------------
__global__ void __launch_bounds__(384) k4_pass2(const float* __restrict__ feat_query,
                                                const float* __restrict__ x_query,
                                                const float* __restrict__ x_shot,
                                                float* __restrict__ out) {
    __shared__ float map_s[N_ * T_];
    __shared__ float4 part4[4 * N_ * 96];
    __shared__ float accf[N_ * C_];
    __shared__ float red[160];

    int q = blockIdx.x, b = blockIdx.y, tid = threadIdx.x;
    int bq = b * Q_ + q;
    size_t nt_base = (size_t)bq * N_ * T_;

    float mx[N_];
    #pragma unroll
    for (int n = 0; n < N_; n++) mx[n] = -1e30f;
    if (tid < T_) {
        float nqv = g_nq[bq * T_ + tid];
        #pragma unroll
        for (int n = 0; n < N_; n++) {
            float denom = fmaxf(nqv * g_ns[(b * N_ + n) * T_ + tid], 1e-8f);
            mx[n] = g_num[nt_base + n * T_ + tid] / denom;
        }
    }
    blockReduceMaxArr<N_>(mx, red, tid);
    if (tid == 0) {
        float lg = (mx[0] + mx[1] + mx[2] + mx[3] + mx[4]) * (1.f / N_);
        out[bq] = lg;
        out[B_ * Q_ + bq] = lg;
    }

    for (int i = tid; i < N_ * T_; i += 384) map_s[i] = sigmoidf(g_dq[nt_base + i]);
    __syncthreads();

    int g = tid / 96, cg = tid % 96;
    float4 acc[N_];
    #pragma unroll
    for (int n = 0; n < N_; n++) acc[n] = make_float4(0.f, 0.f, 0.f, 0.f);
    const float* fqp = feat_query + ((size_t)bq * T_ + g * 49) * C_ + 4 * cg;
    float4 nf = *(const float4*)fqp;
    for (int t = 0; t < 49; t++) {
        float4 f = nf;
        if (t + 1 < 49) nf = *(const float4*)(fqp + (size_t)(t + 1) * C_);
        int tg = g * 49 + t;
        #pragma unroll
        for (int n = 0; n < N_; n++) {
            float m = map_s[n * T_ + tg];
            acc[n].x += f.x * m; acc[n].y += f.y * m;
            acc[n].z += f.z * m; acc[n].w += f.w * m;
        }
    }
    #pragma unroll
    for (int n = 0; n < N_; n++) part4[(g * N_ + n) * 96 + cg] = acc[n];
    __syncthreads();
    for (int idx = tid; idx < N_ * 96; idx += 384) {
        int n = idx / 96, c4 = idx % 96;
        float4 s0 = part4[(0 * N_ + n) * 96 + c4];
        float4 s1 = part4[(1 * N_ + n) * 96 + c4];
        float4 s2 = part4[(2 * N_ + n) * 96 + c4];
        float4 s3 = part4[(3 * N_ + n) * 96 + c4];
        float4 s;
        s.x = s0.x + s1.x + s2.x + s3.x;
        s.y = s0.y + s1.y + s2.y + s3.y;
        s.z = s0.z + s1.z + s2.z + s3.z;
        s.w = s0.w + s1.w + s2.w + s3.w;
        *(float4*)&accf[n * C_ + 4 * c4] = s;
    }
    __syncthreads();

    int c = tid;
    float ysum[N_], wcv[N_];
    #pragma unroll
    for (int n = 0; n < N_; n++) {
        const float* p = g_accp + (size_t)((b * N_ + n) * SCH_) * C_ + c;
        float s0 = 0.f, s1 = 0.f, s2 = 0.f, s3 = 0.f;
        s0 += p[(size_t)0 * C_]; s1 += p[(size_t)1 * C_];
        s2 += p[(size_t)2 * C_]; s3 += p[(size_t)3 * C_];
        s0 += p[(size_t)4 * C_]; s1 += p[(size_t)5 * C_];
        s2 += p[(size_t)6 * C_]; s3 += p[(size_t)7 * C_];
        ysum[n] = (s0 + s1) + (s2 + s3);
        wcv[n] = g_wc[(b * N_ + n) * C_ + c];
    }
    #pragma unroll
    for (int n = 0; n < N_; n++) {
        float v = wcv[n] * accf[n * C_ + c] * (1.f / T_);
        float y = wcv[n] * ysum[n] * (1.f / T_);
        float pr[3] = { v * v, v * y, y * y };
        blockReduceSumArr<3>(pr, red, tid);
        if (tid == 0)
            out[2 * B_ * Q_ + B_ * Q_ * N_ + bq * N_ + n] =
                pr[1] / ((1e-16f + sqrtf(pr[0])) * (1e-16f + sqrtf(pr[2])));
    }

    float xv = x_query[(size_t)bq * C_ + c];
    float xsv[N_];
    #pragma unroll
    for (int n = 0; n < N_; n++) xsv[n] = x_shot[(size_t)(b * N_ + n) * C_ + c];
    float pr11[11];
    pr11[0] = xv * xv;
    #pragma unroll
    for (int n = 0; n < N_; n++) {
        pr11[1 + n] = xv * xsv[n];
        pr11[6 + n] = xsv[n] * xsv[n];
    }
    blockReduceSumArr<11>(pr11, red, tid);
    if (tid == 0) {
        float qn = fmaxf(sqrtf(pr11[0]), 1e-12f);
        #pragma unroll
        for (int n = 0; n < N_; n++) {
            float sn = fmaxf(sqrtf(pr11[6 + n]), 1e-12f);
            out[2 * B_ * Q_ + bq * N_ + n] = TEMP_ * pr11[1 + n] / (qn * sn);
        }
    }
}

// ---------------- launch (6 nodes) ----------------
extern "C" void kernel_launch(void* const* d_in, const int* in_sizes, int n_in,
                              void* d_out, int out_size) {
    const float* feat_shot  = (const float*)d_in[0];
    const float* feat_query = (const float*)d_in[1];
    const float* x_shot     = (const float*)d_in[2];
    const float* x_query    = (const float*)d_in[3];
    const float* w1_task    = (const float*)d_in[4];
    const float* b1_task    = (const float*)d_in[5];
    const float* w2_task    = (const float*)d_in[6];
    const float* b2_task    = (const float*)d_in[7];
    const float* w1_cls     = (const float*)d_in[8];
    const float* b1_cls     = (const float*)d_in[9];
    const float* w2_cls     = (const float*)d_in[10];
    const float* b2_cls     = (const float*)d_in[11];
    float* out = (float*)d_out;

    k1_partial<<<dim3(TCH_, B_ * N_), C_>>>(feat_shot);
    k2_mlp1<<<H_ / 32, 256>>>(w1_task, b1_task, w1_cls, b1_cls);
    k2_mlp2A<<<dim3(3, 12, JCH_), 512>>>(w2_task, w2_cls);
    k2c_shot<<<dim3(SCH_, B_ * N_), 384>>>(feat_shot, b2_task, b2_cls);
    k3_pass1<<<dim3(98, B_), 256>>>(feat_query, feat_shot);
    k4_pass2<<<dim3(Q_, B_), 384>>>(feat_query, x_query, x_shot, out);
}

// round 16
// speedup vs baseline: 1.6513x; 1.0881x over previous
#include <cuda_runtime.h>
#include <math.h>

#define DEV_INLINE __device__ __forceinline__

constexpr int B_ = 2, Q_ = 75, N_ = 5, T_ = 196, C_ = 384, H_ = 1536;
constexpr float TEMP_ = 10.0f;
constexpr int TCH_ = 14;                  // t-chunks for k1 (14*14=196)
constexpr int JCH_ = 8;                   // j-chunks for mlp2 (8*192=1536)
constexpr int SCH_ = 8;                   // t-chunks for k2c (4x25 + 4x24)
constexpr int GRID_F = 148;               // fused kernel grid (1 block/SM)

// ---------------- scratch (device globals; no allocation) ----------------
__device__ float g_part[B_ * N_ * TCH_ * C_];
__device__ float g_hidden[(B_ + B_ * N_) * H_]; // rows 0..1 task, 2..11 cls
__device__ float g_p2[JCH_ * 12 * C_];          // mlp2 partials [jchunk][row][c]
__device__ float g_wc[B_ * N_ * C_];
__device__ float g_u[B_ * N_ * C_];
__device__ float g_ns[B_ * N_ * T_];
__device__ float g_accp[B_ * N_ * SCH_ * C_];   // shot-side t-partials
__device__ float g_num[B_ * Q_ * N_ * T_];
__device__ float g_dq[B_ * Q_ * N_ * T_];
__device__ float g_nq[B_ * Q_ * T_];

// software grid barrier state (self-resetting; epoch monotonic -> replay-safe)
__device__ int g_bar_count = 0;
__device__ int g_bar_epoch = 0;

DEV_INLINE void gridBarrier(int nblocks) {
    __threadfence();            // make this thread's prior writes device-visible
    __syncthreads();            // all block threads' writes done + fenced
    if (threadIdx.x == 0) {
        int old = atomicAdd(&g_bar_epoch, 0);      // L2-coherent read BEFORE arrival
        int ticket = atomicAdd(&g_bar_count, 1);
        if (ticket == nblocks - 1) {
            g_bar_count = 0;
            __threadfence();
            atomicAdd(&g_bar_epoch, 1);
        } else {
            while (atomicAdd(&g_bar_epoch, 0) == old) __nanosleep(64);
        }
    }
    __syncthreads();
}

// ---------------- reduction helpers ----------------
DEV_INLINE float blockReduceSum1(float v, float* red, int tid) {
    #pragma unroll
    for (int o = 16; o; o >>= 1) v += __shfl_xor_sync(0xffffffffu, v, o);
    int warp = tid >> 5, lane = tid & 31;
    int nw = blockDim.x >> 5;
    __syncthreads();
    if (lane == 0) red[warp] = v;
    __syncthreads();
    if (tid == 0) {
        float s = 0.f;
        for (int w = 0; w < nw; w++) s += red[w];
        red[0] = s;
    }
    __syncthreads();
    float r = red[0];
    __syncthreads();
    return r;
}

template <int NV>
DEV_INLINE void blockReduceSumArr(float* v, float* red, int tid) {
    #pragma unroll
    for (int i = 0; i < NV; i++)
        #pragma unroll
        for (int o = 16; o; o >>= 1) v[i] += __shfl_xor_sync(0xffffffffu, v[i], o);
    int warp = tid >> 5, lane = tid & 31;
    int nw = blockDim.x >> 5;
    __syncthreads();
    if (lane == 0)
        #pragma unroll
        for (int i = 0; i < NV; i++) red[warp * NV + i] = v[i];
    __syncthreads();
    if (tid == 0) {
        for (int w = 1; w < nw; w++)
            #pragma unroll
            for (int i = 0; i < NV; i++) red[i] += red[w * NV + i];
    }
    __syncthreads();
    #pragma unroll
    for (int i = 0; i < NV; i++) v[i] = red[i];
    __syncthreads();
}

template <int NV>
DEV_INLINE void blockReduceMaxArr(float* v, float* red, int tid) {
    #pragma unroll
    for (int i = 0; i < NV; i++)
        #pragma unroll
        for (int o = 16; o; o >>= 1) v[i] = fmaxf(v[i], __shfl_xor_sync(0xffffffffu, v[i], o));
    int warp = tid >> 5, lane = tid & 31;
    int nw = blockDim.x >> 5;
    __syncthreads();
    if (lane == 0)
        #pragma unroll
        for (int i = 0; i < NV; i++) red[warp * NV + i] = v[i];
    __syncthreads();
    if (tid == 0) {
        for (int w = 1; w < nw; w++)
            #pragma unroll
            for (int i = 0; i < NV; i++) red[i] = fmaxf(red[i], red[w * NV + i]);
    }
    __syncthreads();
    #pragma unroll
    for (int i = 0; i < NV; i++) v[i] = red[i];
    __syncthreads();
}

DEV_INLINE float sigmoidf(float x) { return 1.f / (1.f + expf(-x)); }

// ---------------- FUSED: k1 + mlp1 + mlp2A + k2c (1 kernel, 3 grid barriers) ----------------
__global__ void __launch_bounds__(512, 1) fused_shot(
    const float* __restrict__ feat_shot,
    const float* __restrict__ w1t, const float* __restrict__ b1t,
    const float* __restrict__ w1c, const float* __restrict__ b1c,
    const float* __restrict__ w2t, const float* __restrict__ w2c,
    const float* __restrict__ b2t, const float* __restrict__ b2c)
{
    __shared__ __align__(16) float sm[10752];   // 43 KB, aliased per phase
    int blk = blockIdx.x, tid = threadIdx.x;

    // ===== Phase 1: k1 partial sums (140 units) =====
    if (blk < B_ * N_ * TCH_ && tid < C_) {
        int bn = blk / TCH_, chunk = blk % TCH_;
        const float* p = feat_shot + ((size_t)bn * T_ + chunk * 14) * C_ + tid;
        float s0 = 0.f, s1 = 0.f;
        #pragma unroll
        for (int t = 0; t < 14; t += 2) {
            s0 += p[(size_t)t * C_];
            s1 += p[(size_t)(t + 1) * C_];
        }
        g_part[(bn * TCH_ + chunk) * C_ + tid] = s0 + s1;
    }
    gridBarrier(GRID_F);

    // ===== Phase 2: mlp1 (48 units; 16 warps x 24 c) =====
    if (blk < 48) {
        float* xs = sm;               // 12*C = 4608
        float* part = sm + 12 * C_;   // 16*12*32 = 6144
        for (int i = tid; i < 10 * C_; i += 512) {
            int bn = i / C_, c = i % C_;
            const float* p = g_part + (size_t)bn * TCH_ * C_ + c;
            float a0 = 0.f, a1 = 0.f;
            #pragma unroll
            for (int k = 0; k < TCH_; k += 2) {
                a0 += p[(size_t)k * C_];
                a1 += p[(size_t)(k + 1) * C_];
            }
            xs[(2 + bn) * C_ + c] = (a0 + a1) * (1.f / T_);
        }
        __syncthreads();
        for (int i = tid; i < 2 * C_; i += 512) {
            int r = i / C_, c = i % C_;
            float s = 0.f;
            #pragma unroll
            for (int n = 0; n < N_; n++) s += xs[(2 + r * N_ + n) * C_ + c];
            xs[r * C_ + c] = s * (1.f / N_);
        }
        __syncthreads();
        int w = tid >> 5, l = tid & 31;
        int j = blk * 32 + l;
        float acc[12];
        #pragma unroll
        for (int r = 0; r < 12; r++) acc[r] = 0.f;
        int c0 = w * 24;
        float nwt = w1t[(size_t)c0 * H_ + j];
        float nwc = w1c[(size_t)c0 * H_ + j];
        for (int c = c0; c < c0 + 24; c++) {
            float wt = nwt, wc = nwc;
            if (c + 1 < c0 + 24) {
                nwt = w1t[(size_t)(c + 1) * H_ + j];
                nwc = w1c[(size_t)(c + 1) * H_ + j];
            }
            acc[0] += xs[0 * C_ + c] * wt;
            acc[1] += xs[1 * C_ + c] * wt;
            #pragma unroll
            for (int r = 2; r < 12; r++) acc[r] += xs[r * C_ + c] * wc;
        }
        #pragma unroll
        for (int r = 0; r < 12; r++) part[(w * 12 + r) * 32 + l] = acc[r];
        __syncthreads();
        for (int idx = tid; idx < 12 * 32; idx += 512) {
            int r = idx / 32, ll = idx % 32;
            float s = 0.f;
            #pragma unroll
            for (int ww = 0; ww < 16; ww++) s += part[(ww * 12 + r) * 32 + ll];
            int jj = blk * 32 + ll;
            float bias = (r < B_) ? b1t[jj] : b1c[jj];
            g_hidden[r * H_ + jj] = fmaxf(s + bias, 0.f);
        }
    }
    gridBarrier(GRID_F);

    // ===== Phase 3: mlp2A (288 units, <=2 per block) =====
    {
        float* hid_s = sm;                      // 192
        float4* part4 = (float4*)(sm + 192);    // 16*32 float4
        #pragma unroll
        for (int rep = 0; rep < 2; rep++) {
            int u = blk + rep * GRID_F;
            __syncthreads();   // protect smem reuse across reps (uniform branch per block)
            if (u < 3 * 12 * JCH_) {
                int ct = u % 3, rem = u / 3;
                int row = rem % 12, z = rem / 12;
                if (tid < 192) hid_s[tid] = g_hidden[row * H_ + z * 192 + tid];
                __syncthreads();
                int jg = tid >> 5, q = tid & 31;
                int cbase = ct * 128 + q * 4;
                const float* w2 = (row < B_) ? w2t : w2c;
                int jl0 = jg * 12;
                const float* wp = w2 + (size_t)(z * 192 + jl0) * C_ + cbase;
                float4 a = make_float4(0.f, 0.f, 0.f, 0.f);
                float4 nf = *(const float4*)wp;
                #pragma unroll
                for (int jj = 0; jj < 12; jj++) {
                    float4 f = nf;
                    if (jj + 1 < 12) nf = *(const float4*)(wp + (size_t)(jj + 1) * C_);
                    float m = hid_s[jl0 + jj];
                    a.x += f.x * m; a.y += f.y * m; a.z += f.z * m; a.w += f.w * m;
                }
                part4[jg * 32 + q] = a;
                __syncthreads();
                if (tid < 32) {
                    float4 s = part4[tid];
                    #pragma unroll
                    for (int g = 1; g < 16; g++) {
                        float4 t = part4[g * 32 + tid];
                        s.x += t.x; s.y += t.y; s.z += t.z; s.w += t.w;
                    }
                    *(float4*)&g_p2[(size_t)(z * 12 + row) * C_ + ct * 128 + tid * 4] = s;
                }
            }
        }
    }
    gridBarrier(GRID_F);

    // ===== Phase 4: k2c shot-side (80 units) =====
    if (blk < SCH_ * B_ * N_) {
        int tg = blk & 7, bn = blk >> 3, b = bn / N_;
        float* u_s = sm;                 // 384
        float* fs_s = sm + 384;          // 25*384 = 9600
        float* map_s = sm + 384 + 9600;  // 25
        int warp = tid >> 5, lane = tid & 31;
        int start = (tg < 4) ? tg * 25 : 100 + (tg - 4) * 24;
        int len = (tg < 4) ? 25 : 24;

        // mlp2B fold (c = tid < 384)
        if (tid < C_) {
            int c = tid;
            const float* pc = g_p2 + (size_t)(2 + bn) * C_ + c;
            const float* pt = g_p2 + (size_t)b * C_ + c;
            float s0 = 0.f, s1 = 0.f, s2 = 0.f, s3 = 0.f;
            float r0 = 0.f, r1 = 0.f, r2 = 0.f, r3 = 0.f;
            #pragma unroll
            for (int z = 0; z < JCH_; z += 4) {
                s0 += pc[(size_t)(z + 0) * 12 * C_];
                s1 += pc[(size_t)(z + 1) * 12 * C_];
                s2 += pc[(size_t)(z + 2) * 12 * C_];
                s3 += pc[(size_t)(z + 3) * 12 * C_];
                r0 += pt[(size_t)(z + 0) * 12 * C_];
                r1 += pt[(size_t)(z + 1) * 12 * C_];
                r2 += pt[(size_t)(z + 2) * 12 * C_];
                r3 += pt[(size_t)(z + 3) * 12 * C_];
            }
            float wc = sigmoidf((s0 + s1) + (s2 + s3) + b2c[c]);
            float wt = (r0 + r1) + (r2 + r3) + b2t[c];
            float uv = wc * wt;
            u_s[c] = uv;
            if (tg == 0) {
                g_wc[bn * C_ + c] = wc;
                g_u[bn * C_ + c] = uv;
            }
        }

        // stage contiguous chunk (float4 copy over 512 threads)
        const float* fsr = feat_shot + ((size_t)bn * T_ + start) * C_;
        {
            const float4* src4 = (const float4*)fsr;
            float4* dst4 = (float4*)fs_s;
            int n4 = len * (C_ / 4);
            for (int idx = tid; idx < n4; idx += 512) dst4[idx] = src4[idx];
        }
        __syncthreads();

        // per-t norms + map logits (16 warps stride t)
        for (int i = warp; i < len; i += 16) {
            float ss = 0.f, du = 0.f;
            for (int cc = lane; cc < C_; cc += 32) {
                float f = fs_s[i * C_ + cc];
                ss += f * f;
                du += f * u_s[cc];
            }
            #pragma unroll
            for (int o = 16; o; o >>= 1) {
                ss += __shfl_xor_sync(0xffffffffu, ss, o);
                du += __shfl_xor_sync(0xffffffffu, du, o);
            }
            if (lane == 0) {
                g_ns[bn * T_ + start + i] = sqrtf(ss);
                map_s[i] = sigmoidf(du);
            }
        }
        __syncthreads();

        // t-partial acc
        if (tid < C_) {
            float a = 0.f;
            for (int i = 0; i < len; i++) a += fs_s[i * C_ + tid] * map_s[i];
            g_accp[(size_t)(bn * SCH_ + tg) * C_ + tid] = a;
        }
    }
}

// ---------------- K3: pass 1 (unchanged) ----------------
__global__ void __launch_bounds__(256) k3_pass1(const float* __restrict__ feat_query,
                                                const float* __restrict__ feat_shot) {
    __shared__ float fs_s[2 * N_ * C_];
    __shared__ float u_s[N_ * C_];
    int b = blockIdx.y, t0 = blockIdx.x * 2, tid = threadIdx.x;
    for (int i = tid; i < 2 * N_ * C_; i += 256) {
        int tt = i / (N_ * C_), r = i % (N_ * C_);
        int n = r / C_, c = r % C_;
        fs_s[i] = feat_shot[((size_t)(b * N_ + n) * T_ + t0 + tt) * C_ + c];
    }
    for (int i = tid; i < N_ * C_; i += 256) u_s[i] = g_u[b * N_ * C_ + i];
    __syncthreads();

    int warp = tid >> 5, lane = tid & 31;
    for (int task = warp; task < 38; task += 8) {
        int tt = task / 19, qi = task % 19;
        int t = t0 + tt, q0 = qi * 4;

        float4 fq[4][3];
        #pragma unroll
        for (int qq = 0; qq < 4; qq++) {
            int q = q0 + qq;
            if (q < Q_) {
                const float* p = feat_query + (((size_t)(b * Q_ + q)) * T_ + t) * C_;
                #pragma unroll
                for (int j = 0; j < 3; j++)
                    fq[qq][j] = *(const float4*)(p + 4 * (lane + 32 * j));
            } else {
                #pragma unroll
                for (int j = 0; j < 3; j++) fq[qq][j] = make_float4(0.f, 0.f, 0.f, 0.f);
            }
        }

        float acc[44];
        #pragma unroll
        for (int i = 0; i < 44; i++) acc[i] = 0.f;

        #pragma unroll
        for (int j = 0; j < 3; j++) {
            int cb = 4 * (lane + 32 * j);
            #pragma unroll
            for (int n = 0; n < N_; n++) {
                float4 s4 = *(const float4*)&fs_s[(tt * N_ + n) * C_ + cb];
                float4 u4 = *(const float4*)&u_s[n * C_ + cb];
                #pragma unroll
                for (int qq = 0; qq < 4; qq++) {
                    float4 f = fq[qq][j];
                    acc[qq * 5 + n]      += f.x * s4.x + f.y * s4.y + f.z * s4.z + f.w * s4.w;
                    acc[20 + qq * 5 + n] += f.x * u4.x + f.y * u4.y + f.z * u4.z + f.w * u4.w;
                }
            }
            #pragma unroll
            for (int qq = 0; qq < 4; qq++) {
                float4 f = fq[qq][j];
                acc[40 + qq] += f.x * f.x + f.y * f.y + f.z * f.z + f.w * f.w;
            }
        }

        #pragma unroll
        for (int i = 0; i < 44; i++)
            #pragma unroll
            for (int o = 16; o; o >>= 1) acc[i] += __shfl_xor_sync(0xffffffffu, acc[i], o);

        if (lane == 0) {
            #pragma unroll
            for (int qq = 0; qq < 4; qq++) {
                int q = q0 + qq;
                if (q < Q_) {
                    size_t base = (size_t)(b * Q_ + q) * N_ * T_;
                    #pragma unroll
                    for (int n = 0; n < N_; n++) {
                        g_num[base + n * T_ + t] = acc[qq * 5 + n];
                        g_dq[base + n * T_ + t]  = acc[20 + qq * 5 + n];
                    }
                    g_nq[(b * Q_ + q) * T_ + t] = sqrtf(acc[40 + qq]);
                }
            }
        }
    }
}

// ---------------- K4: pass 2 (combines shot partials + both normalizations) ----------------
__global__ void __launch_bounds__(384) k4_pass2(const float* __restrict__ feat_query,
                                                const float* __restrict__ x_query,
                                                const float* __restrict__ x_shot,
                                                float* __restrict__ out) {
    __shared__ float map_s[N_ * T_];
    __shared__ float4 part4[4 * N_ * 96];
    __shared__ float accf[N_ * C_];
    __shared__ float red[160];

    int q = blockIdx.x, b = blockIdx.y, tid = threadIdx.x;
    int bq = b * Q_ + q;
    size_t nt_base = (size_t)bq * N_ * T_;

    float mx[N_];
    #pragma unroll
    for (int n = 0; n < N_; n++) mx[n] = -1e30f;
    if (tid < T_) {
        float nqv = g_nq[bq * T_ + tid];
        #pragma unroll
        for (int n = 0; n < N_; n++) {
            float denom = fmaxf(nqv * g_ns[(b * N_ + n) * T_ + tid], 1e-8f);
            mx[n] = g_num[nt_base + n * T_ + tid] / denom;
        }
    }
    blockReduceMaxArr<N_>(mx, red, tid);
    if (tid == 0) {
        float lg = (mx[0] + mx[1] + mx[2] + mx[3] + mx[4]) * (1.f / N_);
        out[bq] = lg;
        out[B_ * Q_ + bq] = lg;
    }

    for (int i = tid; i < N_ * T_; i += 384) map_s[i] = sigmoidf(g_dq[nt_base + i]);
    __syncthreads();

    int g = tid / 96, cg = tid % 96;
    float4 acc[N_];
    #pragma unroll
    for (int n = 0; n < N_; n++) acc[n] = make_float4(0.f, 0.f, 0.f, 0.f);
    const float* fqp = feat_query + ((size_t)bq * T_ + g * 49) * C_ + 4 * cg;
    float4 nf = *(const float4*)fqp;
    for (int t = 0; t < 49; t++) {
        float4 f = nf;
        if (t + 1 < 49) nf = *(const float4*)(fqp + (size_t)(t + 1) * C_);
        int tg = g * 49 + t;
        #pragma unroll
        for (int n = 0; n < N_; n++) {
            float m = map_s[n * T_ + tg];
            acc[n].x += f.x * m; acc[n].y += f.y * m;
            acc[n].z += f.z * m; acc[n].w += f.w * m;
        }
    }
    #pragma unroll
    for (int n = 0; n < N_; n++) part4[(g * N_ + n) * 96 + cg] = acc[n];
    __syncthreads();
    for (int idx = tid; idx < N_ * 96; idx += 384) {
        int n = idx / 96, c4 = idx % 96;
        float4 s0 = part4[(0 * N_ + n) * 96 + c4];
        float4 s1 = part4[(1 * N_ + n) * 96 + c4];
        float4 s2 = part4[(2 * N_ + n) * 96 + c4];
        float4 s3 = part4[(3 * N_ + n) * 96 + c4];
        float4 s;
        s.x = s0.x + s1.x + s2.x + s3.x;
        s.y = s0.y + s1.y + s2.y + s3.y;
        s.z = s0.z + s1.z + s2.z + s3.z;
        s.w = s0.w + s1.w + s2.w + s3.w;
        *(float4*)&accf[n * C_ + 4 * c4] = s;
    }
    __syncthreads();

    int c = tid;
    float ysum[N_], wcv[N_];
    #pragma unroll
    for (int n = 0; n < N_; n++) {
        const float* p = g_accp + (size_t)((b * N_ + n) * SCH_) * C_ + c;
        float s0 = 0.f, s1 = 0.f, s2 = 0.f, s3 = 0.f;
        s0 += p[(size_t)0 * C_]; s1 += p[(size_t)1 * C_];
        s2 += p[(size_t)2 * C_]; s3 += p[(size_t)3 * C_];
        s0 += p[(size_t)4 * C_]; s1 += p[(size_t)5 * C_];
        s2 += p[(size_t)6 * C_]; s3 += p[(size_t)7 * C_];
        ysum[n] = (s0 + s1) + (s2 + s3);
        wcv[n] = g_wc[(b * N_ + n) * C_ + c];
    }
    #pragma unroll
    for (int n = 0; n < N_; n++) {
        float v = wcv[n] * accf[n * C_ + c] * (1.f / T_);
        float y = wcv[n] * ysum[n] * (1.f / T_);
        float pr[3] = { v * v, v * y, y * y };
        blockReduceSumArr<3>(pr, red, tid);
        if (tid == 0)
            out[2 * B_ * Q_ + B_ * Q_ * N_ + bq * N_ + n] =
                pr[1] / ((1e-16f + sqrtf(pr[0])) * (1e-16f + sqrtf(pr[2])));
    }

    float xv = x_query[(size_t)bq * C_ + c];
    float xsv[N_];
    #pragma unroll
    for (int n = 0; n < N_; n++) xsv[n] = x_shot[(size_t)(b * N_ + n) * C_ + c];
    float pr11[11];
    pr11[0] = xv * xv;
    #pragma unroll
    for (int n = 0; n < N_; n++) {
        pr11[1 + n] = xv * xsv[n];
        pr11[6 + n] = xsv[n] * xsv[n];
    }
    blockReduceSumArr<11>(pr11, red, tid);
    if (tid == 0) {
        float qn = fmaxf(sqrtf(pr11[0]), 1e-12f);
        #pragma unroll
        for (int n = 0; n < N_; n++) {
            float sn = fmaxf(sqrtf(pr11[6 + n]), 1e-12f);
            out[2 * B_ * Q_ + bq * N_ + n] = TEMP_ * pr11[1 + n] / (qn * sn);
        }
    }
}

// ---------------- launch (3 nodes) ----------------
extern "C" void kernel_launch(void* const* d_in, const int* in_sizes, int n_in,
                              void* d_out, int out_size) {
    const float* feat_shot  = (const float*)d_in[0];
    const float* feat_query = (const float*)d_in[1];
    const float* x_shot     = (const float*)d_in[2];
    const float* x_query    = (const float*)d_in[3];
    const float* w1_task    = (const float*)d_in[4];
    const float* b1_task    = (const float*)d_in[5];
    const float* w2_task    = (const float*)d_in[6];
    const float* b2_task    = (const float*)d_in[7];
    const float* w1_cls     = (const float*)d_in[8];
    const float* b1_cls     = (const float*)d_in[9];
    const float* w2_cls     = (const float*)d_in[10];
    const float* b2_cls     = (const float*)d_in[11];
    float* out = (float*)d_out;

    fused_shot<<<GRID_F, 512>>>(feat_shot, w1_task, b1_task, w1_cls, b1_cls,
                                w2_task, w2_cls, b2_task, b2_cls);
    k3_pass1<<<dim3(98, B_), 256>>>(feat_query, feat_shot);
    k4_pass2<<<dim3(Q_, B_), 384>>>(feat_query, x_query, x_shot, out);
}